// round 15
// baseline (speedup 1.0000x reference)
#include <cuda_runtime.h>
#include <cstdint>
#include <math.h>

#define NB 4
#define LQ 128
#define DIM 128
#define HID 512
#define WWIN 5
#define MAXSEG 44
#define MAXINT 384
#define OW (2 + 2*LQ*DIM)   // 32770 floats per batch row

#define CL 16               // cluster size (CTAs per batch chain)
#define TPB2 512
#define MTP 516             // padded row stride (2064B, 16B-mult)

#define ENC_IPB 4
#define ENC_SMEM ((DIM*DIM + 2*ENC_IPB*DIM)*4)   // w-stage + e + h = 69632 B

typedef unsigned long long ull;

// ---------------- device scratch (no allocations allowed) ----------------
static __device__ float g_enc[NB*LQ*DIM];
static __device__ float g_jsd[NB*LQ];
static __device__ int   g_nInt[NB];
static __device__ float g_dt[NB*MAXINT];
static __device__ int   g_envSeg[NB*MAXINT];
static __device__ int   g_gsel[NB*LQ];
static __device__ int   g_segS[NB*MAXSEG];
static __device__ int   g_segE[NB*MAXSEG];
static __device__ float g_M[HID*HID];      // M = W1z · W3  (512x512)
static __device__ float g_zfin[NB*DIM];

__device__ __forceinline__ float softplusf(float x){
    return fmaxf(x, 0.f) + log1pf(expf(-fabsf(x)));
}

__device__ __forceinline__ bool is_index_arr(const void* p){
    int v = ((const int*)p)[0];
    return (v >= 0 && v < 1000000);
}

__device__ __forceinline__ uint32_t smem_u32(const void* p){
    return (uint32_t)__cvta_generic_to_shared(p);
}
__device__ __forceinline__ uint32_t mapa_u32(uint32_t la, uint32_t rank){
    uint32_t ra;
    asm volatile("mapa.shared::cluster.u32 %0, %1, %2;" : "=r"(ra) : "r"(la), "r"(rank));
    return ra;
}
__device__ __forceinline__ void st_async_f(uint32_t raddr, uint32_t rmbar, float v){
    asm volatile("st.async.shared::cluster.mbarrier::complete_tx::bytes.b32 [%0], %1, [%2];"
                 :: "r"(raddr), "r"(__float_as_uint(v)), "r"(rmbar) : "memory");
}
__device__ __forceinline__ void mbar_init(uint32_t mbar, uint32_t cnt){
    asm volatile("mbarrier.init.shared.b64 [%0], %1;" :: "r"(mbar), "r"(cnt) : "memory");
}
__device__ __forceinline__ void mbar_inval(uint32_t mbar){
    asm volatile("mbarrier.inval.shared.b64 [%0];" :: "r"(mbar) : "memory");
}
__device__ __forceinline__ void mbar_expect(uint32_t mbar, uint32_t bytes){
    asm volatile("mbarrier.arrive.expect_tx.shared.b64 _, [%0], %1;"
                 :: "r"(mbar), "r"(bytes) : "memory");
}
// cta-scope acquire: st.async data lands in LOCAL smem; completion carries visibility.
__device__ __forceinline__ void mbar_wait(uint32_t mbar, uint32_t parity){
    asm volatile("{\n\t"
        ".reg .pred P;\n\t"
        "LW%=:\n\t"
        "mbarrier.try_wait.parity.acquire.cta.shared::cta.b64 P, [%0], %1, 0x989680;\n\t"
        "@P bra LD%=;\n\t"
        "bra LW%=;\n\t"
        "LD%=:\n\t"
        "}" :: "r"(mbar), "r"(parity) : "memory");
}

// packed f32x2 fma
__device__ __forceinline__ ull ffma2(ull a, ull b, ull c){
    ull d;
    asm("fma.rn.f32x2 %0, %1, %2, %3;" : "=l"(d) : "l"(a), "l"(b), "l"(c));
    return d;
}
__device__ __forceinline__ float unpack_sum(ull a){
    return __uint_as_float((unsigned)(a & 0xffffffffu)) + __uint_as_float((unsigned)(a >> 32));
}
__device__ __forceinline__ ull pack2(float lo, float hi){
    return (ull)__float_as_uint(lo) | ((ull)__float_as_uint(hi) << 32);
}

#define CLUSTER_SYNC_() do { \
    asm volatile("barrier.cluster.arrive.aligned;" ::: "memory"); \
    asm volatile("barrier.cluster.wait.aligned;" ::: "memory"); } while(0)

// ---------------- kernel 1: encoder, 4 items/block, smem-staged weights ----------------
extern __shared__ float enc_s[];
__global__ void enc_k(const int* __restrict__ hi, const float* __restrict__ emb,
                      const float* __restrict__ w1, const float* __restrict__ b1,
                      const float* __restrict__ w2, const float* __restrict__ b2,
                      float* __restrict__ out)
{
    float* ws   = enc_s;
    float* ebuf = enc_s + DIM*DIM;
    float* hbuf = ebuf + ENC_IPB*DIM;
    int t = threadIdx.x;
    int b = blockIdx.y;
    int l0 = blockIdx.x * ENC_IPB;

    for (int i = t; i < ENC_IPB*DIM; i += 128){
        int it = i >> 7, d = i & 127;
        ebuf[it*DIM + d] = emb[(size_t)hi[b*LQ + l0 + it]*DIM + d];
    }
    for (int i = 4*t; i < DIM*DIM; i += 512)
        *(float4*)&ws[i] = *(const float4*)&w1[i];
    __syncthreads();

    float acc[ENC_IPB];
#pragma unroll
    for (int it = 0; it < ENC_IPB; it++) acc[it] = b1[t];
    for (int k = 0; k < DIM; k++){
        float wv = ws[k*DIM + t];
#pragma unroll
        for (int it = 0; it < ENC_IPB; it++)
            acc[it] = fmaf(ebuf[it*DIM + k], wv, acc[it]);
    }
    __syncthreads();
#pragma unroll
    for (int it = 0; it < ENC_IPB; it++) hbuf[it*DIM + t] = fmaxf(acc[it], 0.f);
    for (int i = 4*t; i < DIM*DIM; i += 512)
        *(float4*)&ws[i] = *(const float4*)&w2[i];
    __syncthreads();

#pragma unroll
    for (int it = 0; it < ENC_IPB; it++) acc[it] = b2[t];
    for (int k = 0; k < DIM; k++){
        float wv = ws[k*DIM + t];
#pragma unroll
        for (int it = 0; it < ENC_IPB; it++)
            acc[it] = fmaf(hbuf[it*DIM + k], wv, acc[it]);
    }
#pragma unroll
    for (int it = 0; it < ENC_IPB; it++){
        int l = l0 + it;
        g_enc[(b*LQ + l)*DIM + t] = acc[it];
        out[(size_t)b*OW + 2 + LQ*DIM + l*DIM + t] = acc[it];
    }
}

// ---------------- kernel 1bc: fused M=W1z*W3 (blocks 0..63) + JSD (blocks 64..) ----------------
__global__ void pre_k(const float* __restrict__ vw1, const float* __restrict__ vw3,
                      const int* __restrict__ hl)
{
    __shared__ float w3r[8*128];
    int t = threadIdx.x;
    int bx = blockIdx.x;

    if (bx < 64){
        int j0 = bx * 8;
        for (int i = t; i < 8*128; i += 128) w3r[i] = vw3[j0*128 + i];
        __syncthreads();
        float acc[8][4];
#pragma unroll
        for (int jj = 0; jj < 8; jj++)
#pragma unroll
            for (int q = 0; q < 4; q++) acc[jj][q] = 0.f;
        for (int k = 0; k < 128; k++){
            float w1v[4];
#pragma unroll
            for (int q = 0; q < 4; q++) w1v[q] = vw1[k*HID + t + q*128];
#pragma unroll
            for (int jj = 0; jj < 8; jj++){
                float w3v = w3r[jj*128 + k];
#pragma unroll
                for (int q = 0; q < 4; q++) acc[jj][q] = fmaf(w3v, w1v[q], acc[jj][q]);
            }
        }
        for (int jj = 0; jj < 8; jj++)
#pragma unroll
            for (int q = 0; q < 4; q++)
                g_M[(size_t)(j0 + jj)*HID + t + q*128] = acc[jj][q];
        return;
    }

    int idx = bx - 64;
    int b = idx >> 5;
    int w = t >> 5, l = t & 31;
    int j = (idx & 31)*4 + w;
    int n = hl[b]; if (n > LQ) n = LQ;
    if (n < 2*WWIN || j > n - 2*WWIN) return;

    const float4* base = (const float4*)&g_enc[(b*LQ + j)*DIM];
    float4 sL = make_float4(0.f,0.f,0.f,0.f), sR = sL;
#pragma unroll
    for (int r = 0; r < WWIN; r++){
        float4 vL = base[r*32 + l];
        float4 vR = base[(WWIN + r)*32 + l];
        sL.x += vL.x; sL.y += vL.y; sL.z += vL.z; sL.w += vL.w;
        sR.x += vR.x; sR.y += vR.y; sR.z += vR.z; sR.w += vR.w;
    }
    const float inv = 1.f/(float)WWIN;
    sL.x *= inv; sL.y *= inv; sL.z *= inv; sL.w *= inv;
    sR.x *= inv; sR.y *= inv; sR.z *= inv; sR.w *= inv;

    float mL = fmaxf(fmaxf(sL.x, sL.y), fmaxf(sL.z, sL.w));
    float mR = fmaxf(fmaxf(sR.x, sR.y), fmaxf(sR.z, sR.w));
#pragma unroll
    for (int o = 16; o > 0; o >>= 1){
        mL = fmaxf(mL, __shfl_xor_sync(0xffffffffu, mL, o));
        mR = fmaxf(mR, __shfl_xor_sync(0xffffffffu, mR, o));
    }
    float eL0 = expf(sL.x - mL), eL1 = expf(sL.y - mL), eL2 = expf(sL.z - mL), eL3 = expf(sL.w - mL);
    float eR0 = expf(sR.x - mR), eR1 = expf(sR.y - mR), eR2 = expf(sR.z - mR), eR3 = expf(sR.w - mR);
    float suL = (eL0 + eL1) + (eL2 + eL3);
    float suR = (eR0 + eR1) + (eR2 + eR3);
#pragma unroll
    for (int o = 16; o > 0; o >>= 1){
        suL += __shfl_xor_sync(0xffffffffu, suL, o);
        suR += __shfl_xor_sync(0xffffffffu, suR, o);
    }
    float p0 = eL0/suL + 1e-8f, p1 = eL1/suL + 1e-8f, p2 = eL2/suL + 1e-8f, p3 = eL3/suL + 1e-8f;
    float q0 = eR0/suR + 1e-8f, q1 = eR1/suR + 1e-8f, q2 = eR2/suR + 1e-8f, q3 = eR3/suR + 1e-8f;
    float ps = (p0 + p1) + (p2 + p3);
    float qs = (q0 + q1) + (q2 + q3);
#pragma unroll
    for (int o = 16; o > 0; o >>= 1){
        ps += __shfl_xor_sync(0xffffffffu, ps, o);
        qs += __shfl_xor_sync(0xffffffffu, qs, o);
    }
    p0 /= ps; p1 /= ps; p2 /= ps; p3 /= ps;
    q0 /= qs; q1 /= qs; q2 /= qs; q3 /= qs;
    float c = 0.f;
    {
        float m0 = 0.5f*(p0+q0); c += 0.5f*p0*logf(p0/m0) + 0.5f*q0*logf(q0/m0);
        float m1 = 0.5f*(p1+q1); c += 0.5f*p1*logf(p1/m1) + 0.5f*q1*logf(q1/m1);
        float m2 = 0.5f*(p2+q2); c += 0.5f*p2*logf(p2/m2) + 0.5f*q2*logf(q2/m2);
        float m3 = 0.5f*(p3+q3); c += 0.5f*p3*logf(p3/m3) + 0.5f*q3*logf(q3/m3);
    }
#pragma unroll
    for (int o = 16; o > 0; o >>= 1) c += __shfl_xor_sync(0xffffffffu, c, o);
    if (l == 0) g_jsd[b*LQ + j] = c;
}

// ---------------- kernel 2: ballot replay + closed-form parallel grid build ----------------
__global__ void plan_k(const float* __restrict__ ht, const int* __restrict__ hl,
                       const void* __restrict__ p16, const void* __restrict__ p17,
                       const void* __restrict__ p18)
{
    int b = blockIdx.x, t = threadIdx.x;
    const float* pt;
    if (is_index_arr(p16)) pt = (const float*)p18;   // order: pos,neg,pt
    else                   pt = (const float*)p16;   // order: pt,pos,neg

    __shared__ double times[LQ];
    __shared__ unsigned trig[4];
    __shared__ double bounds[MAXSEG + 2];
    __shared__ int starts[MAXSEG + 1];
    __shared__ int mArr[MAXSEG + 1];
    __shared__ int cumArr[MAXSEG + 1];
    __shared__ int segBase[MAXSEG + 1];
    __shared__ int snb, sns, dupF, gapF, sE;
    __shared__ double ev[LQ + 2*MAXSEG + 4];

    int n = hl[b]; if (n > LQ) n = LQ;
    int lim = n - 2*WWIN;
    if (t < n) times[t] = (double)ht[b*LQ + t];
    if (t == 0){ snb = 1; sns = 1; bounds[0] = (double)ht[b*LQ]; starts[0] = 0; dupF = 0; gapF = 0; }
    {
        float jv = (t < LQ) ? g_jsd[b*LQ + t] : 0.f;
        unsigned bal = __ballot_sync(0xffffffffu, (t <= lim) && (jv > 0.5f));
        if ((t & 31) == 0) trig[t >> 5] = bal;
    }
    __syncthreads();
    {
        bool d = (t > 0 && t < n) && (times[t] == times[t-1]);
        if (__ballot_sync(0xffffffffu, d)) dupF = 1;
    }

    if (t == 0 && n >= 2*WWIN){
        int j = 0;
        for (;;){
            if (j > lim) break;
            int wi = j >> 5, sh = j & 31;
            unsigned m = trig[wi];
            if (sh) m &= (0xffffffffu << sh);
            while (!m && wi < 3){ wi++; m = trig[wi]; }
            if (!m) break;
            int f = (wi << 5) + __ffs(m) - 1;
            if (f > lim) break;
            bounds[snb] = 0.5*(times[f + WWIN - 1] + times[f + WWIN]);
            snb++;
            starts[sns] = f + WWIN; sns++;
            j = f + WWIN;
        }
    }
    __syncthreads();
    if (t == 0){
        if (times[n-1] > bounds[snb-1]) { bounds[snb] = times[n-1]; snb++; }
    }
    __syncthreads();

    int nseg = sns, nb2 = snb;

    if (!dupF){
        if (t < nseg){
            int si = t;
            int s = starts[si];
            int e = (si + 1 < nseg) ? starts[si+1] - 1 : n - 1;
            g_segS[b*MAXSEG + si] = s; g_segE[b*MAXSEG + si] = e;
            int d0 = (si == 0) ? 1 : 0;
            int d1 = (si == nseg - 1) ? 1 : 0;
            mArr[si] = (e - s + 1) + 2 - d0 - d1;
        }
        __syncthreads();
        if (t == 0){
            int sb = 0, cum = 0;
            for (int si = 0; si < nseg; si++){
                segBase[si] = sb; cumArr[si] = cum;
                sb += mArr[si]; cum += mArr[si] - 1;
            }
            sE = sb;
            double lb = bounds[nb2-1];
            double ptb = (double)pt[b];
            if (ptb > lb + 1e-6){
                double t1 = ptb;
                if (t1 - lb < 1e-6) t1 = lb + 1e-6;
                g_dt[b*MAXINT + cum] = (float)(t1 - lb);
                g_envSeg[b*MAXINT + cum] = nseg - 1;
                cum++;
            }
            g_nInt[b] = cum;
        }
        __syncthreads();
        int E = sE;
        for (int g = t; g < E; g += 128){
            int si = 0;
            while (si + 1 < nseg && segBase[si+1] <= g) si++;
            int k = g - segBase[si];
            int s = starts[si], d0 = (si == 0) ? 1 : 0;
            double v;
            if (k == 0) v = bounds[si];
            else if (si < nseg - 1 && k == mArr[si] - 1) v = bounds[si+1];
            else v = times[s + d0 + k - 1];
            ev[g] = v;
        }
        __syncthreads();
        {
            bool bad = false;
            for (int g = t; g < E; g += 128){
                int si = 0;
                while (si + 1 < nseg && segBase[si+1] <= g) si++;
                if (g > segBase[si] && ev[g] - ev[g-1] < 1e-6) bad = true;
            }
            if (__ballot_sync(0xffffffffu, bad)) gapF = 1;
        }
        __syncthreads();
        if (gapF && t < nseg){
            int base = segBase[t], m = mArr[t];
            for (int k = 1; k < m; k++)
                if (ev[base + k] - ev[base + k - 1] < 1e-6) ev[base + k] = ev[base + k - 1] + 1e-6;
        }
        if (gapF) __syncthreads();
        for (int g = t; g < E; g += 128){
            int si = 0;
            while (si + 1 < nseg && segBase[si+1] <= g) si++;
            int k = g - segBase[si];
            if (k < mArr[si] - 1){
                g_dt[b*MAXINT + cumArr[si] + k] = (float)(ev[g+1] - ev[g]);
                g_envSeg[b*MAXINT + cumArr[si] + k] = si;
            }
        }
        if (t < n){
            int si = 0;
            while (si + 1 < nseg && starts[si+1] <= t) si++;
            int base = segBase[si], m = mArr[si];
            double ti = times[t];
            int best = 0; double bd = fabs(ev[base] - ti);
            for (int k = 1; k < m; k++){
                double dd = fabs(ev[base + k] - ti);
                if (dd < bd){ bd = dd; best = k; }
            }
            g_gsel[b*LQ + t] = cumArr[si] + best;
        }
    } else {
        if (t < nseg){
            int si = t;
            int s = starts[si];
            int e = (si + 1 < nseg) ? starts[si+1] - 1 : n - 1;
            g_segS[b*MAXSEG + si] = s; g_segE[b*MAXSEG + si] = e;
            double t0 = bounds[si];
            double t1 = (si + 1 < nb2) ? bounds[si+1] : bounds[nb2-1];
            int base = s + 2*si;
            int m = 0; ev[base + m++] = t0;
            for (int i = s; i <= e; i++){
                double d = times[i];
                if (d >= t0 && d <= t1 && d != ev[base + m - 1]) ev[base + m++] = d;
            }
            if (t1 != ev[base + m - 1]) ev[base + m++] = t1;
            for (int k = 1; k < m; k++)
                if (ev[base + k] - ev[base + k - 1] < 1e-6) ev[base + k] = ev[base + k - 1] + 1e-6;
            mArr[si] = m;
        }
        __syncthreads();
        if (t == 0){
            int cum = 0;
            for (int si = 0; si < nseg; si++){ cumArr[si] = cum; cum += mArr[si] - 1; }
            double lb = bounds[nb2-1];
            double ptb = (double)pt[b];
            if (ptb > lb + 1e-6){
                double t1 = ptb;
                if (t1 - lb < 1e-6) t1 = lb + 1e-6;
                g_dt[b*MAXINT + cum] = (float)(t1 - lb);
                g_envSeg[b*MAXINT + cum] = nseg - 1;
                cum++;
            }
            g_nInt[b] = cum;
        }
        __syncthreads();
        if (t < nseg){
            int si = t, base = starts[si] + 2*si;
            int m = mArr[si], cum = cumArr[si];
            for (int k = 0; k < m - 1; k++){
                g_dt[b*MAXINT + cum + k] = (float)(ev[base + k + 1] - ev[base + k]);
                g_envSeg[b*MAXINT + cum + k] = si;
            }
        }
        if (t < n){
            int si = 0;
            while (si + 1 < nseg && starts[si+1] <= t) si++;
            int base = starts[si] + 2*si;
            int m = mArr[si], cum = cumArr[si];
            double ti = times[t];
            int best = 0; double bd = fabs(ev[base] - ti);
            for (int k = 1; k < m; k++){
                double dd = fabs(ev[base + k] - ti);
                if (dd < bd){ bd = dd; best = k; }
            }
            g_gsel[b*LQ + t] = cum + best;
        }
    }
}

// ---------------- kernel 3: clustered Euler ODE (syncless exchange epilogues) ----------------
struct __align__(16) OdeSmem {
    unsigned long long mb[4];   // 0: h1, 1: h2, rest pad
    float mt[32*MTP];           // M slice transposed [o][j] (66KB); staging at init
    float w3s[8*MTP];           // W3 slice [i][j]
    float cenvAll[MAXSEG*32];
    float env[DIM];             // z0 staging
    float h1[HID];              // receive buffer (chunk x written by CTA x)
    float h2[HID];              // receive buffer
    float pA[2][512];           // L2 partials, [o][q] layout, parity-buffered
    float pB[2][512];           // M partials, [o][q] layout, parity-buffered
    float p2[16*8];             // W3 partials
    float zs[8];
    float b2s[32];
    float c3s[32];
    float b3s[8];
    float aval[32];
    float dtv[MAXINT];
    int   eseg[MAXINT];
    int   segS[MAXSEG];
    int   segE[MAXSEG];
    int   gsel[LQ];
};

extern __shared__ __align__(16) char ode_raw[];

#define XCHG_TX (2048u)   // 16 ranks x 32 floats x 4B per phase

__global__ void __launch_bounds__(TPB2, 1) __cluster_dims__(CL, 1, 1)
ode_cl_k(const float* __restrict__ usert, const int* __restrict__ u,
         const float* __restrict__ vw1, const float* __restrict__ vb1,
         const float* __restrict__ vw2, const float* __restrict__ vb2,
         const float* __restrict__ vw3, const float* __restrict__ vb3,
         const int* __restrict__ hl,
         float* __restrict__ out)
{
    OdeSmem* S = (OdeSmem*)ode_raw;
    int t = threadIdx.x;
    uint32_t cr; asm("mov.u32 %0, %%cluster_ctarank;" : "=r"(cr));
    int b = blockIdx.x / CL;

    const int o32 = t & 31, p16g = t >> 5;   // 32 outs x 16 k-parts; p16g = warp = send rank
    const int o8w = t & 7,  i64  = t >> 3;   // traj-write mapping

    // ---- layer-2 weight slice into registers (32 floats = 16 f32x2) ----
    ull w2p[16];
    {
        const float* base = &vw2[(size_t)(p16g*32)*HID + cr*32 + o32];
#pragma unroll
        for (int m = 0; m < 16; m++)
            w2p[m] = pack2(base[(size_t)(2*m)*HID], base[(size_t)(2*m+1)*HID]);
    }

    // ---- stage W1 z-half & env-half slices in mt space (freed before mt load) ----
    float* wz   = S->mt;              // [128][32]
    float* wenv = S->mt + 4096;       // [128][32]
    for (int idx = t; idx < 4096; idx += TPB2){
        int k = idx >> 5, o = idx & 31;
        wz[k*32 + o]   = vw1[(size_t)k*HID + cr*32 + o];
        wenv[k*32 + o] = vw1[(size_t)(DIM + k)*HID + cr*32 + o];
    }
    if (t < DIM) S->env[t] = usert[(size_t)u[b]*DIM + t];   // z0
    for (int i = t; i < MAXINT; i += TPB2){
        S->dtv[i]  = g_dt[b*MAXINT + i];
        S->eseg[i] = g_envSeg[b*MAXINT + i];
    }
    for (int i = t; i < MAXSEG; i += TPB2){
        S->segS[i] = g_segS[b*MAXSEG + i];
        S->segE[i] = g_segE[b*MAXSEG + i];
    }
    for (int i = t; i < LQ; i += TPB2) S->gsel[i] = g_gsel[b*LQ + i];
    if (t < 32) S->b2s[t] = vb2[cr*32 + t];
    if (t < 8)  S->b3s[t] = vb3[cr*8 + t];
    __syncthreads();

    // ---- a0 = W1z·z0 and c3 = W1z·b3 (16 k-parts of 8) into pA[0]/pB[0] scratch ----
    {
        float az = 0.f, ac = 0.f;
        const float* wp = &wz[(p16g*8)*32 + o32];
        const float* zp = &S->env[p16g*8];
#pragma unroll
        for (int kk = 0; kk < 8; kk++){
            float wv = wp[kk*32];
            az = fmaf(zp[kk], wv, az);
            ac = fmaf(vb3[p16g*8 + kk], wv, ac);
        }
        S->pA[0][p16g*32 + o32] = az;
        S->pB[0][p16g*32 + o32] = ac;
    }
    __syncthreads();
    if (t < 32){
        float sa = 0.f, sc = 0.f;
#pragma unroll
        for (int q = 0; q < 16; q++){ sa += S->pA[0][q*32 + t]; sc += S->pB[0][q*32 + t]; }
        S->aval[t] = sa; S->c3s[t] = sc;
    }
    __syncthreads();

    int nInt = g_nInt[b];
    int nseg = S->eseg[nInt - 1] + 1;
    int n = hl[b]; if (n > LQ) n = LQ;

    // ---- per-segment cenv = vb1 + Wenv·mean(enc[s..e]) ----
    for (int si = 0; si < nseg; si++){
        int s = S->segS[si], e = S->segE[si];
        if (t < DIM){
            float a = 0.f;
            for (int r2 = s; r2 <= e; r2++) a += g_enc[(b*LQ + r2)*DIM + t];
            S->h1[t] = a / (float)(e - s + 1);
        }
        __syncthreads();
        {
            float a = 0.f;
            const float* wp = &wenv[(p16g*8)*32 + o32];
            const float* ep = &S->h1[p16g*8];
#pragma unroll
            for (int kk = 0; kk < 8; kk++) a = fmaf(ep[kk], wp[kk*32], a);
            S->pA[0][p16g*32 + o32] = a;
        }
        __syncthreads();
        if (t < 32){
            float sa = 0.f;
#pragma unroll
            for (int q = 0; q < 16; q++) sa += S->pA[0][q*32 + t];
            S->cenvAll[si*32 + t] = vb1[cr*32 + t] + sa;
        }
        __syncthreads();
    }

    // ---- load M slice (overwrites staging) + W3 slice + z slice ----
    for (int idx = t; idx < 32*HID; idx += TPB2){
        int jj = idx >> 5, o = idx & 31;
        S->mt[o*MTP + jj] = g_M[(size_t)jj*HID + cr*32 + o];
    }
    for (int idx = t; idx < 8*HID; idx += TPB2){
        int jj = idx >> 3, o = idx & 7;
        S->w3s[o*MTP + jj] = vw3[jj*DIM + cr*8 + o];
    }
    if (t < 8) S->zs[t] = S->env[cr*8 + t];

    uint32_t mb_h1 = smem_u32(&S->mb[0]);
    uint32_t mb_h2 = smem_u32(&S->mb[1]);
    if (t == 0){ mbar_init(mb_h1, 1); mbar_init(mb_h2, 1); }
    __syncthreads();
    if (t == 0){ mbar_expect(mb_h1, XCHG_TX); mbar_expect(mb_h2, XCHG_TX); }
    __syncthreads();
    CLUSTER_SYNC_();

    // per-thread recurrent state registers (16-way redundant, identical arithmetic)
    float avreg = S->aval[o32];
    float c3reg = S->c3s[o32];
    float b2reg = S->b2s[o32];

    uint32_t ra_h1 = mapa_u32(smem_u32(&S->h1[cr*32 + o32]), p16g);
    uint32_t ra_h2 = mapa_u32(smem_u32(&S->h2[cr*32 + o32]), p16g);
    uint32_t rb_h1 = mapa_u32(mb_h1, p16g);
    uint32_t rb_h2 = mapa_u32(mb_h2, p16g);

    // grid-0 state writes (z0 slice)
    {
#pragma unroll
        for (int pass = 0; pass < 2; pass++){
            int i = pass*64 + i64;
            if (i < n && S->gsel[i] == 0)
                out[(size_t)b*OW + 2 + (size_t)i*DIM + cr*8 + o8w] = S->zs[o8w];
        }
    }

    int totalSS = 2*nInt;
    // prologue: per-thread h1 compute + send for substep 0 (self-send fills local buffer)
    {
        float hv = softplusf(S->cenvAll[S->eseg[0]*32 + o32] + avreg);
        st_async_f(ra_h1, rb_h1, hv);
    }

    for (int ss = 0; ss < totalSS; ss++){
        int j = ss >> 1;
        float dtsub = 0.5f * S->dtv[j];
        uint32_t par = (uint32_t)(ss & 1);
        float* pa = S->pA[par];
        float* pb = S->pB[par];

        mbar_wait(mb_h1, par);
        if (t == 0) mbar_expect(mb_h1, XCHG_TX);
        // ---- layer 2: 32 out x 512 k, f32x2 packed, weights in registers ----
        {
            const ulonglong2* hr = (const ulonglong2*)&S->h1[p16g*32];
            ull acc0 = 0ull, acc1 = 0ull;
#pragma unroll
            for (int m = 0; m < 8; m++){
                ulonglong2 h = hr[m];
                acc0 = ffma2(w2p[2*m],   h.x, acc0);
                acc1 = ffma2(w2p[2*m+1], h.y, acc1);
            }
            pa[o32*16 + p16g] = unpack_sum(acc0) + unpack_sum(acc1);
        }
        __syncthreads();   // A: L2 partials complete
        {
            const float* pr = &pa[o32*16];
            float sa = 0.f;
#pragma unroll
            for (int q = 0; q < 16; q++) sa += pr[q];
            float hv = softplusf(b2reg + sa);
            st_async_f(ra_h2, rb_h2, hv);
        }
        mbar_wait(mb_h2, par);
        if (t == 0) mbar_expect(mb_h2, XCHG_TX);
        // ---- M·h2 partials (all threads) + W3·h2 partials (t<128) ----
        {
            const ulonglong2* wr = (const ulonglong2*)&S->mt[o32*MTP + p16g*32];
            const ulonglong2* hr = (const ulonglong2*)&S->h2[p16g*32];
            ull acc0 = 0ull, acc1 = 0ull;
#pragma unroll
            for (int m = 0; m < 8; m++){
                ulonglong2 w = wr[m];
                ulonglong2 h = hr[m];
                acc0 = ffma2(w.x, h.x, acc0);
                acc1 = ffma2(w.y, h.y, acc1);
            }
            pb[o32*16 + p16g] = unpack_sum(acc0) + unpack_sum(acc1);
        }
        if (t < 128){
            int o8d = t & 7, pp = t >> 3;
            const ulonglong2* wr = (const ulonglong2*)&S->w3s[o8d*MTP + pp*32];
            const ulonglong2* hr = (const ulonglong2*)&S->h2[pp*32];
            ull acc0 = 0ull;
#pragma unroll
            for (int m = 0; m < 8; m++){
                ulonglong2 w = wr[m];
                ulonglong2 h = hr[m];
                acc0 = ffma2(w.x, h.x, acc0);
                acc0 = ffma2(w.y, h.y, acc0);
            }
            S->p2[pp*8 + o8d] = unpack_sum(acc0);
        }
        __syncthreads();   // B: M + W3 partials complete
        {
            const float* pr = &pb[o32*16];
            float tot = 0.f;
#pragma unroll
            for (int q = 0; q < 16; q++) tot += pr[q];
            avreg += dtsub * (c3reg + tot);
            if (ss + 1 < totalSS){
                int jn = (ss + 1) >> 1;
                float hv = softplusf(S->cenvAll[S->eseg[jn]*32 + o32] + avreg);
                st_async_f(ra_h1, rb_h1, hv);
            }
        }
        if (t < 8){
            float dv = S->b3s[t];
#pragma unroll
            for (int q = 0; q < 16; q++) dv += S->p2[q*8 + t];
            S->zs[t] += dtsub * dv;
        }
        if (ss & 1){   // end of interval j: write matched interaction states
            __syncthreads();   // C: zs visible to all traj writers
            int g = j + 1;
#pragma unroll
            for (int pass = 0; pass < 2; pass++){
                int i = pass*64 + i64;
                if (i < n && S->gsel[i] == g)
                    out[(size_t)b*OW + 2 + (size_t)i*DIM + cr*8 + o8w] = S->zs[o8w];
            }
        }
    }

    __syncthreads();
    if (t < 8) g_zfin[b*DIM + cr*8 + t] = S->zs[t];
    CLUSTER_SYNC_();
    if (t == 0){ mbar_inval(mb_h1); mbar_inval(mb_h2); }
}

// ---------------- kernel 4: scores ----------------
__global__ void score_k(const float* __restrict__ emb,
                        const void* __restrict__ p16, const void* __restrict__ p17,
                        const void* __restrict__ p18, float* __restrict__ out)
{
    int b = blockIdx.x, t = threadIdx.x;   // 128 threads
    const int *pos, *neg;
    if (is_index_arr(p16)) { pos = (const int*)p16; neg = (const int*)p17; }
    else                   { pos = (const int*)p17; neg = (const int*)p18; }
    __shared__ float sb[8];
    float z = g_zfin[b*DIM + t];
    for (int which = 0; which < 2; which++){
        const int* pn = which ? neg : pos;
        float v = z * emb[(size_t)pn[b]*DIM + t];
#pragma unroll
        for (int o = 16; o > 0; o >>= 1) v += __shfl_xor_sync(0xffffffffu, v, o);
        if ((t & 31) == 0) sb[t >> 5] = v;
        __syncthreads();
        if (t == 0) out[(size_t)b*OW + which] = (sb[0] + sb[1]) + (sb[2] + sb[3]);
        __syncthreads();
    }
}

// ---------------- launch ----------------
extern "C" void kernel_launch(void* const* d_in, const int* in_sizes, int n_in,
                              void* d_out, int out_size)
{
    const float* emb   = (const float*)d_in[0];
    const float* mw1   = (const float*)d_in[1];
    const float* mb1   = (const float*)d_in[2];
    const float* mw2   = (const float*)d_in[3];
    const float* mb2   = (const float*)d_in[4];
    const float* usert = (const float*)d_in[5];
    const float* vw1   = (const float*)d_in[6];
    const float* vb1   = (const float*)d_in[7];
    const float* vw2   = (const float*)d_in[8];
    const float* vb2   = (const float*)d_in[9];
    const float* vw3   = (const float*)d_in[10];
    const float* vb3   = (const float*)d_in[11];
    const int*   u     = (const int*)d_in[12];
    const int*   hi    = (const int*)d_in[13];
    const float* ht    = (const float*)d_in[14];
    const int*   hl    = (const int*)d_in[15];
    const void*  p16   = d_in[16];
    const void*  p17   = d_in[17];
    const void*  p18   = d_in[18];
    float* out = (float*)d_out;

    static int attrs_set = 0;
    if (!attrs_set){
        cudaFuncSetAttribute(ode_cl_k, cudaFuncAttributeMaxDynamicSharedMemorySize,
                             (int)sizeof(OdeSmem));
        cudaFuncSetAttribute(ode_cl_k, cudaFuncAttributeNonPortableClusterSizeAllowed, 1);
        cudaFuncSetAttribute(enc_k, cudaFuncAttributeMaxDynamicSharedMemorySize, ENC_SMEM);
        attrs_set = 1;
    }

    dim3 ge(LQ/ENC_IPB, NB);
    enc_k<<<ge, DIM, ENC_SMEM>>>(hi, emb, mw1, mb1, mw2, mb2, out);
    pre_k<<<64 + NB*32, 128>>>(vw1, vw3, hl);
    plan_k<<<NB, 128>>>(ht, hl, p16, p17, p18);
    ode_cl_k<<<NB*CL, TPB2, sizeof(OdeSmem)>>>(usert, u, vw1, vb1, vw2, vb2, vw3, vb3,
                                               hl, out);
    score_k<<<NB, 128>>>(emb, p16, p17, p18, out);
}

// round 16
// speedup vs baseline: 1.4808x; 1.4808x over previous
#include <cuda_runtime.h>
#include <cstdint>
#include <math.h>

#define NB 4
#define LQ 128
#define DIM 128
#define HID 512
#define WWIN 5
#define MAXSEG 44
#define MAXINT 384
#define OW (2 + 2*LQ*DIM)   // 32770 floats per batch row

#define CL 16               // cluster size (CTAs per batch chain)
#define TPB2 512
#define MTP 516             // padded row stride (2064B, 16B-mult)
#define PSTR 17             // partials stride: gcd(17,32)=1 -> conflict-free

#define ENC_IPB 4
#define ENC_SMEM ((DIM*DIM + 2*ENC_IPB*DIM)*4)   // w-stage + e + h = 69632 B

typedef unsigned long long ull;

// ---------------- device scratch (no allocations allowed) ----------------
static __device__ float g_enc[NB*LQ*DIM];
static __device__ float g_jsd[NB*LQ];
static __device__ int   g_nInt[NB];
static __device__ float g_dt[NB*MAXINT];
static __device__ int   g_envSeg[NB*MAXINT];
static __device__ int   g_gsel[NB*LQ];
static __device__ int   g_segS[NB*MAXSEG];
static __device__ int   g_segE[NB*MAXSEG];
static __device__ float g_M[HID*HID];      // M = W1z · W3  (512x512)
static __device__ float g_zfin[NB*DIM];

__device__ __forceinline__ float softplusf(float x){
    return fmaxf(x, 0.f) + log1pf(expf(-fabsf(x)));
}

__device__ __forceinline__ bool is_index_arr(const void* p){
    int v = ((const int*)p)[0];
    return (v >= 0 && v < 1000000);
}

__device__ __forceinline__ uint32_t smem_u32(const void* p){
    return (uint32_t)__cvta_generic_to_shared(p);
}
__device__ __forceinline__ uint32_t mapa_u32(uint32_t la, uint32_t rank){
    uint32_t ra;
    asm volatile("mapa.shared::cluster.u32 %0, %1, %2;" : "=r"(ra) : "r"(la), "r"(rank));
    return ra;
}
__device__ __forceinline__ void st_async_f(uint32_t raddr, uint32_t rmbar, float v){
    asm volatile("st.async.shared::cluster.mbarrier::complete_tx::bytes.b32 [%0], %1, [%2];"
                 :: "r"(raddr), "r"(__float_as_uint(v)), "r"(rmbar) : "memory");
}
__device__ __forceinline__ void mbar_init(uint32_t mbar, uint32_t cnt){
    asm volatile("mbarrier.init.shared.b64 [%0], %1;" :: "r"(mbar), "r"(cnt) : "memory");
}
__device__ __forceinline__ void mbar_inval(uint32_t mbar){
    asm volatile("mbarrier.inval.shared.b64 [%0];" :: "r"(mbar) : "memory");
}
__device__ __forceinline__ void mbar_expect(uint32_t mbar, uint32_t bytes){
    asm volatile("mbarrier.arrive.expect_tx.shared.b64 _, [%0], %1;"
                 :: "r"(mbar), "r"(bytes) : "memory");
}
// cta-scope acquire: st.async data lands in LOCAL smem; completion carries visibility.
__device__ __forceinline__ void mbar_wait(uint32_t mbar, uint32_t parity){
    asm volatile("{\n\t"
        ".reg .pred P;\n\t"
        "LW%=:\n\t"
        "mbarrier.try_wait.parity.acquire.cta.shared::cta.b64 P, [%0], %1, 0x989680;\n\t"
        "@P bra LD%=;\n\t"
        "bra LW%=;\n\t"
        "LD%=:\n\t"
        "}" :: "r"(mbar), "r"(parity) : "memory");
}

// packed f32x2 fma
__device__ __forceinline__ ull ffma2(ull a, ull b, ull c){
    ull d;
    asm("fma.rn.f32x2 %0, %1, %2, %3;" : "=l"(d) : "l"(a), "l"(b), "l"(c));
    return d;
}
__device__ __forceinline__ float unpack_sum(ull a){
    return __uint_as_float((unsigned)(a & 0xffffffffu)) + __uint_as_float((unsigned)(a >> 32));
}
__device__ __forceinline__ ull pack2(float lo, float hi){
    return (ull)__float_as_uint(lo) | ((ull)__float_as_uint(hi) << 32);
}

#define CLUSTER_SYNC_() do { \
    asm volatile("barrier.cluster.arrive.aligned;" ::: "memory"); \
    asm volatile("barrier.cluster.wait.aligned;" ::: "memory"); } while(0)

// ---------------- kernel 1: encoder, 4 items/block, smem-staged weights ----------------
extern __shared__ float enc_s[];
__global__ void enc_k(const int* __restrict__ hi, const float* __restrict__ emb,
                      const float* __restrict__ w1, const float* __restrict__ b1,
                      const float* __restrict__ w2, const float* __restrict__ b2,
                      float* __restrict__ out)
{
    float* ws   = enc_s;
    float* ebuf = enc_s + DIM*DIM;
    float* hbuf = ebuf + ENC_IPB*DIM;
    int t = threadIdx.x;
    int b = blockIdx.y;
    int l0 = blockIdx.x * ENC_IPB;

    for (int i = t; i < ENC_IPB*DIM; i += 128){
        int it = i >> 7, d = i & 127;
        ebuf[it*DIM + d] = emb[(size_t)hi[b*LQ + l0 + it]*DIM + d];
    }
    for (int i = 4*t; i < DIM*DIM; i += 512)
        *(float4*)&ws[i] = *(const float4*)&w1[i];
    __syncthreads();

    float acc[ENC_IPB];
#pragma unroll
    for (int it = 0; it < ENC_IPB; it++) acc[it] = b1[t];
    for (int k = 0; k < DIM; k++){
        float wv = ws[k*DIM + t];
#pragma unroll
        for (int it = 0; it < ENC_IPB; it++)
            acc[it] = fmaf(ebuf[it*DIM + k], wv, acc[it]);
    }
    __syncthreads();
#pragma unroll
    for (int it = 0; it < ENC_IPB; it++) hbuf[it*DIM + t] = fmaxf(acc[it], 0.f);
    for (int i = 4*t; i < DIM*DIM; i += 512)
        *(float4*)&ws[i] = *(const float4*)&w2[i];
    __syncthreads();

#pragma unroll
    for (int it = 0; it < ENC_IPB; it++) acc[it] = b2[t];
    for (int k = 0; k < DIM; k++){
        float wv = ws[k*DIM + t];
#pragma unroll
        for (int it = 0; it < ENC_IPB; it++)
            acc[it] = fmaf(hbuf[it*DIM + k], wv, acc[it]);
    }
#pragma unroll
    for (int it = 0; it < ENC_IPB; it++){
        int l = l0 + it;
        g_enc[(b*LQ + l)*DIM + t] = acc[it];
        out[(size_t)b*OW + 2 + LQ*DIM + l*DIM + t] = acc[it];
    }
}

// ---------------- kernel 1bc: fused M=W1z*W3 (blocks 0..63) + JSD (blocks 64..) ----------------
__global__ void pre_k(const float* __restrict__ vw1, const float* __restrict__ vw3,
                      const int* __restrict__ hl)
{
    __shared__ float w3r[8*128];
    int t = threadIdx.x;
    int bx = blockIdx.x;

    if (bx < 64){
        int j0 = bx * 8;
        for (int i = t; i < 8*128; i += 128) w3r[i] = vw3[j0*128 + i];
        __syncthreads();
        float acc[8][4];
#pragma unroll
        for (int jj = 0; jj < 8; jj++)
#pragma unroll
            for (int q = 0; q < 4; q++) acc[jj][q] = 0.f;
        for (int k = 0; k < 128; k++){
            float w1v[4];
#pragma unroll
            for (int q = 0; q < 4; q++) w1v[q] = vw1[k*HID + t + q*128];
#pragma unroll
            for (int jj = 0; jj < 8; jj++){
                float w3v = w3r[jj*128 + k];
#pragma unroll
                for (int q = 0; q < 4; q++) acc[jj][q] = fmaf(w3v, w1v[q], acc[jj][q]);
            }
        }
        for (int jj = 0; jj < 8; jj++)
#pragma unroll
            for (int q = 0; q < 4; q++)
                g_M[(size_t)(j0 + jj)*HID + t + q*128] = acc[jj][q];
        return;
    }

    int idx = bx - 64;
    int b = idx >> 5;
    int w = t >> 5, l = t & 31;
    int j = (idx & 31)*4 + w;
    int n = hl[b]; if (n > LQ) n = LQ;
    if (n < 2*WWIN || j > n - 2*WWIN) return;

    const float4* base = (const float4*)&g_enc[(b*LQ + j)*DIM];
    float4 sL = make_float4(0.f,0.f,0.f,0.f), sR = sL;
#pragma unroll
    for (int r = 0; r < WWIN; r++){
        float4 vL = base[r*32 + l];
        float4 vR = base[(WWIN + r)*32 + l];
        sL.x += vL.x; sL.y += vL.y; sL.z += vL.z; sL.w += vL.w;
        sR.x += vR.x; sR.y += vR.y; sR.z += vR.z; sR.w += vR.w;
    }
    const float inv = 1.f/(float)WWIN;
    sL.x *= inv; sL.y *= inv; sL.z *= inv; sL.w *= inv;
    sR.x *= inv; sR.y *= inv; sR.z *= inv; sR.w *= inv;

    float mL = fmaxf(fmaxf(sL.x, sL.y), fmaxf(sL.z, sL.w));
    float mR = fmaxf(fmaxf(sR.x, sR.y), fmaxf(sR.z, sR.w));
#pragma unroll
    for (int o = 16; o > 0; o >>= 1){
        mL = fmaxf(mL, __shfl_xor_sync(0xffffffffu, mL, o));
        mR = fmaxf(mR, __shfl_xor_sync(0xffffffffu, mR, o));
    }
    float eL0 = expf(sL.x - mL), eL1 = expf(sL.y - mL), eL2 = expf(sL.z - mL), eL3 = expf(sL.w - mL);
    float eR0 = expf(sR.x - mR), eR1 = expf(sR.y - mR), eR2 = expf(sR.z - mR), eR3 = expf(sR.w - mR);
    float suL = (eL0 + eL1) + (eL2 + eL3);
    float suR = (eR0 + eR1) + (eR2 + eR3);
#pragma unroll
    for (int o = 16; o > 0; o >>= 1){
        suL += __shfl_xor_sync(0xffffffffu, suL, o);
        suR += __shfl_xor_sync(0xffffffffu, suR, o);
    }
    float p0 = eL0/suL + 1e-8f, p1 = eL1/suL + 1e-8f, p2 = eL2/suL + 1e-8f, p3 = eL3/suL + 1e-8f;
    float q0 = eR0/suR + 1e-8f, q1 = eR1/suR + 1e-8f, q2 = eR2/suR + 1e-8f, q3 = eR3/suR + 1e-8f;
    float ps = (p0 + p1) + (p2 + p3);
    float qs = (q0 + q1) + (q2 + q3);
#pragma unroll
    for (int o = 16; o > 0; o >>= 1){
        ps += __shfl_xor_sync(0xffffffffu, ps, o);
        qs += __shfl_xor_sync(0xffffffffu, qs, o);
    }
    p0 /= ps; p1 /= ps; p2 /= ps; p3 /= ps;
    q0 /= qs; q1 /= qs; q2 /= qs; q3 /= qs;
    float c = 0.f;
    {
        float m0 = 0.5f*(p0+q0); c += 0.5f*p0*logf(p0/m0) + 0.5f*q0*logf(q0/m0);
        float m1 = 0.5f*(p1+q1); c += 0.5f*p1*logf(p1/m1) + 0.5f*q1*logf(q1/m1);
        float m2 = 0.5f*(p2+q2); c += 0.5f*p2*logf(p2/m2) + 0.5f*q2*logf(q2/m2);
        float m3 = 0.5f*(p3+q3); c += 0.5f*p3*logf(p3/m3) + 0.5f*q3*logf(q3/m3);
    }
#pragma unroll
    for (int o = 16; o > 0; o >>= 1) c += __shfl_xor_sync(0xffffffffu, c, o);
    if (l == 0) g_jsd[b*LQ + j] = c;
}

// ---------------- kernel 2: ballot replay + closed-form parallel grid build ----------------
__global__ void plan_k(const float* __restrict__ ht, const int* __restrict__ hl,
                       const void* __restrict__ p16, const void* __restrict__ p17,
                       const void* __restrict__ p18)
{
    int b = blockIdx.x, t = threadIdx.x;
    const float* pt;
    if (is_index_arr(p16)) pt = (const float*)p18;   // order: pos,neg,pt
    else                   pt = (const float*)p16;   // order: pt,pos,neg

    __shared__ double times[LQ];
    __shared__ unsigned trig[4];
    __shared__ double bounds[MAXSEG + 2];
    __shared__ int starts[MAXSEG + 1];
    __shared__ int mArr[MAXSEG + 1];
    __shared__ int cumArr[MAXSEG + 1];
    __shared__ int segBase[MAXSEG + 1];
    __shared__ int snb, sns, dupF, gapF, sE;
    __shared__ double ev[LQ + 2*MAXSEG + 4];

    int n = hl[b]; if (n > LQ) n = LQ;
    int lim = n - 2*WWIN;
    if (t < n) times[t] = (double)ht[b*LQ + t];
    if (t == 0){ snb = 1; sns = 1; bounds[0] = (double)ht[b*LQ]; starts[0] = 0; dupF = 0; gapF = 0; }
    {
        float jv = (t < LQ) ? g_jsd[b*LQ + t] : 0.f;
        unsigned bal = __ballot_sync(0xffffffffu, (t <= lim) && (jv > 0.5f));
        if ((t & 31) == 0) trig[t >> 5] = bal;
    }
    __syncthreads();
    {
        bool d = (t > 0 && t < n) && (times[t] == times[t-1]);
        if (__ballot_sync(0xffffffffu, d)) dupF = 1;
    }

    if (t == 0 && n >= 2*WWIN){
        int j = 0;
        for (;;){
            if (j > lim) break;
            int wi = j >> 5, sh = j & 31;
            unsigned m = trig[wi];
            if (sh) m &= (0xffffffffu << sh);
            while (!m && wi < 3){ wi++; m = trig[wi]; }
            if (!m) break;
            int f = (wi << 5) + __ffs(m) - 1;
            if (f > lim) break;
            bounds[snb] = 0.5*(times[f + WWIN - 1] + times[f + WWIN]);
            snb++;
            starts[sns] = f + WWIN; sns++;
            j = f + WWIN;
        }
    }
    __syncthreads();
    if (t == 0){
        if (times[n-1] > bounds[snb-1]) { bounds[snb] = times[n-1]; snb++; }
    }
    __syncthreads();

    int nseg = sns, nb2 = snb;

    if (!dupF){
        if (t < nseg){
            int si = t;
            int s = starts[si];
            int e = (si + 1 < nseg) ? starts[si+1] - 1 : n - 1;
            g_segS[b*MAXSEG + si] = s; g_segE[b*MAXSEG + si] = e;
            int d0 = (si == 0) ? 1 : 0;
            int d1 = (si == nseg - 1) ? 1 : 0;
            mArr[si] = (e - s + 1) + 2 - d0 - d1;
        }
        __syncthreads();
        if (t == 0){
            int sb = 0, cum = 0;
            for (int si = 0; si < nseg; si++){
                segBase[si] = sb; cumArr[si] = cum;
                sb += mArr[si]; cum += mArr[si] - 1;
            }
            sE = sb;
            double lb = bounds[nb2-1];
            double ptb = (double)pt[b];
            if (ptb > lb + 1e-6){
                double t1 = ptb;
                if (t1 - lb < 1e-6) t1 = lb + 1e-6;
                g_dt[b*MAXINT + cum] = (float)(t1 - lb);
                g_envSeg[b*MAXINT + cum] = nseg - 1;
                cum++;
            }
            g_nInt[b] = cum;
        }
        __syncthreads();
        int E = sE;
        for (int g = t; g < E; g += 128){
            int si = 0;
            while (si + 1 < nseg && segBase[si+1] <= g) si++;
            int k = g - segBase[si];
            int s = starts[si], d0 = (si == 0) ? 1 : 0;
            double v;
            if (k == 0) v = bounds[si];
            else if (si < nseg - 1 && k == mArr[si] - 1) v = bounds[si+1];
            else v = times[s + d0 + k - 1];
            ev[g] = v;
        }
        __syncthreads();
        {
            bool bad = false;
            for (int g = t; g < E; g += 128){
                int si = 0;
                while (si + 1 < nseg && segBase[si+1] <= g) si++;
                if (g > segBase[si] && ev[g] - ev[g-1] < 1e-6) bad = true;
            }
            if (__ballot_sync(0xffffffffu, bad)) gapF = 1;
        }
        __syncthreads();
        if (gapF && t < nseg){
            int base = segBase[t], m = mArr[t];
            for (int k = 1; k < m; k++)
                if (ev[base + k] - ev[base + k - 1] < 1e-6) ev[base + k] = ev[base + k - 1] + 1e-6;
        }
        if (gapF) __syncthreads();
        for (int g = t; g < E; g += 128){
            int si = 0;
            while (si + 1 < nseg && segBase[si+1] <= g) si++;
            int k = g - segBase[si];
            if (k < mArr[si] - 1){
                g_dt[b*MAXINT + cumArr[si] + k] = (float)(ev[g+1] - ev[g]);
                g_envSeg[b*MAXINT + cumArr[si] + k] = si;
            }
        }
        if (t < n){
            int si = 0;
            while (si + 1 < nseg && starts[si+1] <= t) si++;
            int base = segBase[si], m = mArr[si];
            double ti = times[t];
            int best = 0; double bd = fabs(ev[base] - ti);
            for (int k = 1; k < m; k++){
                double dd = fabs(ev[base + k] - ti);
                if (dd < bd){ bd = dd; best = k; }
            }
            g_gsel[b*LQ + t] = cumArr[si] + best;
        }
    } else {
        if (t < nseg){
            int si = t;
            int s = starts[si];
            int e = (si + 1 < nseg) ? starts[si+1] - 1 : n - 1;
            g_segS[b*MAXSEG + si] = s; g_segE[b*MAXSEG + si] = e;
            double t0 = bounds[si];
            double t1 = (si + 1 < nb2) ? bounds[si+1] : bounds[nb2-1];
            int base = s + 2*si;
            int m = 0; ev[base + m++] = t0;
            for (int i = s; i <= e; i++){
                double d = times[i];
                if (d >= t0 && d <= t1 && d != ev[base + m - 1]) ev[base + m++] = d;
            }
            if (t1 != ev[base + m - 1]) ev[base + m++] = t1;
            for (int k = 1; k < m; k++)
                if (ev[base + k] - ev[base + k - 1] < 1e-6) ev[base + k] = ev[base + k - 1] + 1e-6;
            mArr[si] = m;
        }
        __syncthreads();
        if (t == 0){
            int cum = 0;
            for (int si = 0; si < nseg; si++){ cumArr[si] = cum; cum += mArr[si] - 1; }
            double lb = bounds[nb2-1];
            double ptb = (double)pt[b];
            if (ptb > lb + 1e-6){
                double t1 = ptb;
                if (t1 - lb < 1e-6) t1 = lb + 1e-6;
                g_dt[b*MAXINT + cum] = (float)(t1 - lb);
                g_envSeg[b*MAXINT + cum] = nseg - 1;
                cum++;
            }
            g_nInt[b] = cum;
        }
        __syncthreads();
        if (t < nseg){
            int si = t, base = starts[si] + 2*si;
            int m = mArr[si], cum = cumArr[si];
            for (int k = 0; k < m - 1; k++){
                g_dt[b*MAXINT + cum + k] = (float)(ev[base + k + 1] - ev[base + k]);
                g_envSeg[b*MAXINT + cum + k] = si;
            }
        }
        if (t < n){
            int si = 0;
            while (si + 1 < nseg && starts[si+1] <= t) si++;
            int base = starts[si] + 2*si;
            int m = mArr[si], cum = cumArr[si];
            double ti = times[t];
            int best = 0; double bd = fabs(ev[base] - ti);
            for (int k = 1; k < m; k++){
                double dd = fabs(ev[base + k] - ti);
                if (dd < bd){ bd = dd; best = k; }
            }
            g_gsel[b*LQ + t] = cum + best;
        }
    }
}

// ---------------- kernel 3: clustered Euler ODE (syncless epilogues, padded partials) ----------------
struct __align__(16) OdeSmem {
    unsigned long long mb[4];   // 0: h1, 1: h2, rest pad
    float mt[32*MTP];           // M slice transposed [o][j] (66KB); staging at init
    float w3s[8*MTP];           // W3 slice [i][j]
    float cenvAll[MAXSEG*32];
    float env[DIM];             // z0 staging
    float h1[HID];              // receive buffer (chunk x written by CTA x)
    float h2[HID];              // receive buffer
    float pA[2][32*PSTR];       // L2 partials, [o][q] stride-17, parity-buffered
    float pB[2][32*PSTR];       // M partials, stride-17, parity-buffered
    float p2[16*8];             // W3 partials
    float zs[8];
    float b2s[32];
    float c3s[32];
    float b3s[8];
    float aval[32];
    float dtv[MAXINT];
    int   eseg[MAXINT];
    int   segS[MAXSEG];
    int   segE[MAXSEG];
    int   gsel[LQ];
};

extern __shared__ __align__(16) char ode_raw[];

#define XCHG_TX (2048u)   // 16 ranks x 32 floats x 4B per phase

__global__ void __launch_bounds__(TPB2, 1) __cluster_dims__(CL, 1, 1)
ode_cl_k(const float* __restrict__ usert, const int* __restrict__ u,
         const float* __restrict__ vw1, const float* __restrict__ vb1,
         const float* __restrict__ vw2, const float* __restrict__ vb2,
         const float* __restrict__ vw3, const float* __restrict__ vb3,
         const int* __restrict__ hl,
         float* __restrict__ out)
{
    OdeSmem* S = (OdeSmem*)ode_raw;
    int t = threadIdx.x;
    uint32_t cr; asm("mov.u32 %0, %%cluster_ctarank;" : "=r"(cr));
    int b = blockIdx.x / CL;

    const int o32 = t & 31, p16g = t >> 5;   // 32 outs x 16 k-parts; p16g = warp = send rank
    const int o8w = t & 7,  i64  = t >> 3;   // traj-write mapping

    // ---- layer-2 weight slice into registers (32 floats = 16 f32x2) ----
    ull w2p[16];
    {
        const float* base = &vw2[(size_t)(p16g*32)*HID + cr*32 + o32];
#pragma unroll
        for (int m = 0; m < 16; m++)
            w2p[m] = pack2(base[(size_t)(2*m)*HID], base[(size_t)(2*m+1)*HID]);
    }

    // ---- stage W1 z-half & env-half slices in mt space (freed before mt load) ----
    float* wz   = S->mt;              // [128][32]
    float* wenv = S->mt + 4096;       // [128][32]
    for (int idx = t; idx < 4096; idx += TPB2){
        int k = idx >> 5, o = idx & 31;
        wz[k*32 + o]   = vw1[(size_t)k*HID + cr*32 + o];
        wenv[k*32 + o] = vw1[(size_t)(DIM + k)*HID + cr*32 + o];
    }
    if (t < DIM) S->env[t] = usert[(size_t)u[b]*DIM + t];   // z0
    for (int i = t; i < MAXINT; i += TPB2){
        S->dtv[i]  = g_dt[b*MAXINT + i];
        S->eseg[i] = g_envSeg[b*MAXINT + i];
    }
    for (int i = t; i < MAXSEG; i += TPB2){
        S->segS[i] = g_segS[b*MAXSEG + i];
        S->segE[i] = g_segE[b*MAXSEG + i];
    }
    for (int i = t; i < LQ; i += TPB2) S->gsel[i] = g_gsel[b*LQ + i];
    if (t < 32) S->b2s[t] = vb2[cr*32 + t];
    if (t < 8)  S->b3s[t] = vb3[cr*8 + t];
    __syncthreads();

    // ---- a0 = W1z·z0 and c3 = W1z·b3 (16 k-parts of 8) into pA[0]/pB[0] scratch ----
    {
        float az = 0.f, ac = 0.f;
        const float* wp = &wz[(p16g*8)*32 + o32];
        const float* zp = &S->env[p16g*8];
#pragma unroll
        for (int kk = 0; kk < 8; kk++){
            float wv = wp[kk*32];
            az = fmaf(zp[kk], wv, az);
            ac = fmaf(vb3[p16g*8 + kk], wv, ac);
        }
        S->pA[0][p16g*32 + o32] = az;
        S->pB[0][p16g*32 + o32] = ac;
    }
    __syncthreads();
    if (t < 32){
        float sa = 0.f, sc = 0.f;
#pragma unroll
        for (int q = 0; q < 16; q++){ sa += S->pA[0][q*32 + t]; sc += S->pB[0][q*32 + t]; }
        S->aval[t] = sa; S->c3s[t] = sc;
    }
    __syncthreads();

    int nInt = g_nInt[b];
    int nseg = S->eseg[nInt - 1] + 1;
    int n = hl[b]; if (n > LQ) n = LQ;

    // ---- per-segment cenv = vb1 + Wenv·mean(enc[s..e]) ----
    for (int si = 0; si < nseg; si++){
        int s = S->segS[si], e = S->segE[si];
        if (t < DIM){
            float a = 0.f;
            for (int r2 = s; r2 <= e; r2++) a += g_enc[(b*LQ + r2)*DIM + t];
            S->h1[t] = a / (float)(e - s + 1);
        }
        __syncthreads();
        {
            float a = 0.f;
            const float* wp = &wenv[(p16g*8)*32 + o32];
            const float* ep = &S->h1[p16g*8];
#pragma unroll
            for (int kk = 0; kk < 8; kk++) a = fmaf(ep[kk], wp[kk*32], a);
            S->pA[0][p16g*32 + o32] = a;
        }
        __syncthreads();
        if (t < 32){
            float sa = 0.f;
#pragma unroll
            for (int q = 0; q < 16; q++) sa += S->pA[0][q*32 + t];
            S->cenvAll[si*32 + t] = vb1[cr*32 + t] + sa;
        }
        __syncthreads();
    }

    // ---- load M slice (overwrites staging) + W3 slice + z slice ----
    for (int idx = t; idx < 32*HID; idx += TPB2){
        int jj = idx >> 5, o = idx & 31;
        S->mt[o*MTP + jj] = g_M[(size_t)jj*HID + cr*32 + o];
    }
    for (int idx = t; idx < 8*HID; idx += TPB2){
        int jj = idx >> 3, o = idx & 7;
        S->w3s[o*MTP + jj] = vw3[jj*DIM + cr*8 + o];
    }
    if (t < 8) S->zs[t] = S->env[cr*8 + t];

    uint32_t mb_h1 = smem_u32(&S->mb[0]);
    uint32_t mb_h2 = smem_u32(&S->mb[1]);
    if (t == 0){ mbar_init(mb_h1, 1); mbar_init(mb_h2, 1); }
    __syncthreads();
    if (t == 0){ mbar_expect(mb_h1, XCHG_TX); mbar_expect(mb_h2, XCHG_TX); }
    __syncthreads();
    CLUSTER_SYNC_();

    // per-thread recurrent state registers (16-way redundant, identical arithmetic)
    float avreg = S->aval[o32];
    float c3reg = S->c3s[o32];
    float b2reg = S->b2s[o32];

    uint32_t ra_h1 = mapa_u32(smem_u32(&S->h1[cr*32 + o32]), p16g);
    uint32_t ra_h2 = mapa_u32(smem_u32(&S->h2[cr*32 + o32]), p16g);
    uint32_t rb_h1 = mapa_u32(mb_h1, p16g);
    uint32_t rb_h2 = mapa_u32(mb_h2, p16g);

    // grid-0 state writes (z0 slice)
    {
#pragma unroll
        for (int pass = 0; pass < 2; pass++){
            int i = pass*64 + i64;
            if (i < n && S->gsel[i] == 0)
                out[(size_t)b*OW + 2 + (size_t)i*DIM + cr*8 + o8w] = S->zs[o8w];
        }
    }

    int totalSS = 2*nInt;
    // prologue: per-thread h1 compute + send for substep 0 (self-send fills local buffer)
    {
        float hv = softplusf(S->cenvAll[S->eseg[0]*32 + o32] + avreg);
        st_async_f(ra_h1, rb_h1, hv);
    }

    for (int ss = 0; ss < totalSS; ss++){
        int j = ss >> 1;
        float dtsub = 0.5f * S->dtv[j];
        uint32_t par = (uint32_t)(ss & 1);
        float* pa = S->pA[par];
        float* pb = S->pB[par];

        mbar_wait(mb_h1, par);
        if (t == 0) mbar_expect(mb_h1, XCHG_TX);
        // ---- layer 2: 32 out x 512 k, f32x2 packed, weights in registers ----
        {
            const ulonglong2* hr = (const ulonglong2*)&S->h1[p16g*32];
            ull acc0 = 0ull, acc1 = 0ull;
#pragma unroll
            for (int m = 0; m < 8; m++){
                ulonglong2 h = hr[m];
                acc0 = ffma2(w2p[2*m],   h.x, acc0);
                acc1 = ffma2(w2p[2*m+1], h.y, acc1);
            }
            pa[o32*PSTR + p16g] = unpack_sum(acc0) + unpack_sum(acc1);
        }
        __syncthreads();   // A: L2 partials complete
        {
            const float* pr = &pa[o32*PSTR];
            float sa = 0.f;
#pragma unroll
            for (int q = 0; q < 16; q++) sa += pr[q];
            float hv = softplusf(b2reg + sa);
            st_async_f(ra_h2, rb_h2, hv);
        }
        mbar_wait(mb_h2, par);
        if (t == 0) mbar_expect(mb_h2, XCHG_TX);
        // ---- M·h2 partials (all threads) + W3·h2 partials (t<128) ----
        {
            const ulonglong2* wr = (const ulonglong2*)&S->mt[o32*MTP + p16g*32];
            const ulonglong2* hr = (const ulonglong2*)&S->h2[p16g*32];
            ull acc0 = 0ull, acc1 = 0ull;
#pragma unroll
            for (int m = 0; m < 8; m++){
                ulonglong2 w = wr[m];
                ulonglong2 h = hr[m];
                acc0 = ffma2(w.x, h.x, acc0);
                acc1 = ffma2(w.y, h.y, acc1);
            }
            pb[o32*PSTR + p16g] = unpack_sum(acc0) + unpack_sum(acc1);
        }
        if (t < 128){
            int o8d = t & 7, pp = t >> 3;
            const ulonglong2* wr = (const ulonglong2*)&S->w3s[o8d*MTP + pp*32];
            const ulonglong2* hr = (const ulonglong2*)&S->h2[pp*32];
            ull acc0 = 0ull;
#pragma unroll
            for (int m = 0; m < 8; m++){
                ulonglong2 w = wr[m];
                ulonglong2 h = hr[m];
                acc0 = ffma2(w.x, h.x, acc0);
                acc0 = ffma2(w.y, h.y, acc0);
            }
            S->p2[pp*8 + o8d] = unpack_sum(acc0);
        }
        __syncthreads();   // B: M + W3 partials complete
        {
            const float* pr = &pb[o32*PSTR];
            float tot = 0.f;
#pragma unroll
            for (int q = 0; q < 16; q++) tot += pr[q];
            avreg += dtsub * (c3reg + tot);
            if (ss + 1 < totalSS){
                int jn = (ss + 1) >> 1;
                float hv = softplusf(S->cenvAll[S->eseg[jn]*32 + o32] + avreg);
                st_async_f(ra_h1, rb_h1, hv);
            }
        }
        if (t < 8){
            float dv = S->b3s[t];
#pragma unroll
            for (int q = 0; q < 16; q++) dv += S->p2[q*8 + t];
            S->zs[t] += dtsub * dv;
        }
        if (ss & 1){   // end of interval j: write matched interaction states
            __syncthreads();   // C: zs visible to all traj writers
            int g = j + 1;
#pragma unroll
            for (int pass = 0; pass < 2; pass++){
                int i = pass*64 + i64;
                if (i < n && S->gsel[i] == g)
                    out[(size_t)b*OW + 2 + (size_t)i*DIM + cr*8 + o8w] = S->zs[o8w];
            }
        }
    }

    __syncthreads();
    if (t < 8) g_zfin[b*DIM + cr*8 + t] = S->zs[t];
    CLUSTER_SYNC_();
    if (t == 0){ mbar_inval(mb_h1); mbar_inval(mb_h2); }
}

// ---------------- kernel 4: scores ----------------
__global__ void score_k(const float* __restrict__ emb,
                        const void* __restrict__ p16, const void* __restrict__ p17,
                        const void* __restrict__ p18, float* __restrict__ out)
{
    int b = blockIdx.x, t = threadIdx.x;   // 128 threads
    const int *pos, *neg;
    if (is_index_arr(p16)) { pos = (const int*)p16; neg = (const int*)p17; }
    else                   { pos = (const int*)p17; neg = (const int*)p18; }
    __shared__ float sb[8];
    float z = g_zfin[b*DIM + t];
    for (int which = 0; which < 2; which++){
        const int* pn = which ? neg : pos;
        float v = z * emb[(size_t)pn[b]*DIM + t];
#pragma unroll
        for (int o = 16; o > 0; o >>= 1) v += __shfl_xor_sync(0xffffffffu, v, o);
        if ((t & 31) == 0) sb[t >> 5] = v;
        __syncthreads();
        if (t == 0) out[(size_t)b*OW + which] = (sb[0] + sb[1]) + (sb[2] + sb[3]);
        __syncthreads();
    }
}

// ---------------- launch ----------------
extern "C" void kernel_launch(void* const* d_in, const int* in_sizes, int n_in,
                              void* d_out, int out_size)
{
    const float* emb   = (const float*)d_in[0];
    const float* mw1   = (const float*)d_in[1];
    const float* mb1   = (const float*)d_in[2];
    const float* mw2   = (const float*)d_in[3];
    const float* mb2   = (const float*)d_in[4];
    const float* usert = (const float*)d_in[5];
    const float* vw1   = (const float*)d_in[6];
    const float* vb1   = (const float*)d_in[7];
    const float* vw2   = (const float*)d_in[8];
    const float* vb2   = (const float*)d_in[9];
    const float* vw3   = (const float*)d_in[10];
    const float* vb3   = (const float*)d_in[11];
    const int*   u     = (const int*)d_in[12];
    const int*   hi    = (const int*)d_in[13];
    const float* ht    = (const float*)d_in[14];
    const int*   hl    = (const int*)d_in[15];
    const void*  p16   = d_in[16];
    const void*  p17   = d_in[17];
    const void*  p18   = d_in[18];
    float* out = (float*)d_out;

    static int attrs_set = 0;
    if (!attrs_set){
        cudaFuncSetAttribute(ode_cl_k, cudaFuncAttributeMaxDynamicSharedMemorySize,
                             (int)sizeof(OdeSmem));
        cudaFuncSetAttribute(ode_cl_k, cudaFuncAttributeNonPortableClusterSizeAllowed, 1);
        cudaFuncSetAttribute(enc_k, cudaFuncAttributeMaxDynamicSharedMemorySize, ENC_SMEM);
        attrs_set = 1;
    }

    dim3 ge(LQ/ENC_IPB, NB);
    enc_k<<<ge, DIM, ENC_SMEM>>>(hi, emb, mw1, mb1, mw2, mb2, out);
    pre_k<<<64 + NB*32, 128>>>(vw1, vw3, hl);
    plan_k<<<NB, 128>>>(ht, hl, p16, p17, p18);
    ode_cl_k<<<NB*CL, TPB2, sizeof(OdeSmem)>>>(usert, u, vw1, vb1, vw2, vb2, vw3, vb3,
                                               hl, out);
    score_k<<<NB, 128>>>(emb, p16, p17, p18, out);
}

// round 17
// speedup vs baseline: 1.6155x; 1.0909x over previous
#include <cuda_runtime.h>
#include <cstdint>
#include <math.h>

#define NB 4
#define LQ 128
#define DIM 128
#define HID 512
#define WWIN 5
#define MAXSEG 44
#define MAXINT 384
#define OW (2 + 2*LQ*DIM)   // 32770 floats per batch row

#define CL 16               // cluster size (CTAs per batch chain)
#define TPB2 512
#define MTP 516             // padded row stride (2064B, 16B-mult)

#define ENC_IPB 4
#define ENC_SMEM ((DIM*DIM + 2*ENC_IPB*DIM)*4)

typedef unsigned long long ull;

// ---------------- device scratch (no allocations allowed) ----------------
static __device__ float g_enc[NB*LQ*DIM];
static __device__ float g_jsd[NB*LQ];
static __device__ int   g_nInt[NB];
static __device__ float g_dt[NB*MAXINT];
static __device__ int   g_envSeg[NB*MAXINT];
static __device__ int   g_gsel[NB*LQ];
static __device__ int   g_segS[NB*MAXSEG];
static __device__ int   g_segE[NB*MAXSEG];
static __device__ float g_M[HID*HID];      // M = W1z · W3  (512x512)

__device__ __forceinline__ float softplusf(float x){
    return fmaxf(x, 0.f) + log1pf(expf(-fabsf(x)));
}

__device__ __forceinline__ bool is_index_arr(const void* p){
    int v = ((const int*)p)[0];
    return (v >= 0 && v < 1000000);
}

__device__ __forceinline__ uint32_t smem_u32(const void* p){
    return (uint32_t)__cvta_generic_to_shared(p);
}
__device__ __forceinline__ uint32_t mapa_u32(uint32_t la, uint32_t rank){
    uint32_t ra;
    asm volatile("mapa.shared::cluster.u32 %0, %1, %2;" : "=r"(ra) : "r"(la), "r"(rank));
    return ra;
}
__device__ __forceinline__ void st_async_f(uint32_t raddr, uint32_t rmbar, float v){
    asm volatile("st.async.shared::cluster.mbarrier::complete_tx::bytes.b32 [%0], %1, [%2];"
                 :: "r"(raddr), "r"(__float_as_uint(v)), "r"(rmbar) : "memory");
}
__device__ __forceinline__ void mbar_init(uint32_t mbar, uint32_t cnt){
    asm volatile("mbarrier.init.shared.b64 [%0], %1;" :: "r"(mbar), "r"(cnt) : "memory");
}
__device__ __forceinline__ void mbar_inval(uint32_t mbar){
    asm volatile("mbarrier.inval.shared.b64 [%0];" :: "r"(mbar) : "memory");
}
__device__ __forceinline__ void mbar_expect(uint32_t mbar, uint32_t bytes){
    asm volatile("mbarrier.arrive.expect_tx.shared.b64 _, [%0], %1;"
                 :: "r"(mbar), "r"(bytes) : "memory");
}
// cta-scope acquire: st.async data lands in LOCAL smem; completion carries visibility.
__device__ __forceinline__ void mbar_wait(uint32_t mbar, uint32_t parity){
    asm volatile("{\n\t"
        ".reg .pred P;\n\t"
        "LW%=:\n\t"
        "mbarrier.try_wait.parity.acquire.cta.shared::cta.b64 P, [%0], %1, 0x989680;\n\t"
        "@P bra LD%=;\n\t"
        "bra LW%=;\n\t"
        "LD%=:\n\t"
        "}" :: "r"(mbar), "r"(parity) : "memory");
}

// packed f32x2 fma
__device__ __forceinline__ ull ffma2(ull a, ull b, ull c){
    ull d;
    asm("fma.rn.f32x2 %0, %1, %2, %3;" : "=l"(d) : "l"(a), "l"(b), "l"(c));
    return d;
}
__device__ __forceinline__ float unpack_sum(ull a){
    return __uint_as_float((unsigned)(a & 0xffffffffu)) + __uint_as_float((unsigned)(a >> 32));
}
__device__ __forceinline__ ull pack2(float lo, float hi){
    return (ull)__float_as_uint(lo) | ((ull)__float_as_uint(hi) << 32);
}

#define CLUSTER_SYNC_() do { \
    asm volatile("barrier.cluster.arrive.aligned;" ::: "memory"); \
    asm volatile("barrier.cluster.wait.aligned;" ::: "memory"); } while(0)

// ---------------- kernel 1: encoder, 4 items/block, smem-staged weights ----------------
extern __shared__ float enc_s[];
__global__ void enc_k(const int* __restrict__ hi, const float* __restrict__ emb,
                      const float* __restrict__ w1, const float* __restrict__ b1,
                      const float* __restrict__ w2, const float* __restrict__ b2,
                      float* __restrict__ out)
{
    float* ws   = enc_s;
    float* ebuf = enc_s + DIM*DIM;
    float* hbuf = ebuf + ENC_IPB*DIM;
    int t = threadIdx.x;
    int b = blockIdx.y;
    int l0 = blockIdx.x * ENC_IPB;

    for (int i = t; i < ENC_IPB*DIM; i += 128){
        int it = i >> 7, d = i & 127;
        ebuf[it*DIM + d] = emb[(size_t)hi[b*LQ + l0 + it]*DIM + d];
    }
    for (int i = 4*t; i < DIM*DIM; i += 512)
        *(float4*)&ws[i] = *(const float4*)&w1[i];
    __syncthreads();

    float acc[ENC_IPB];
#pragma unroll
    for (int it = 0; it < ENC_IPB; it++) acc[it] = b1[t];
    for (int k = 0; k < DIM; k++){
        float wv = ws[k*DIM + t];
#pragma unroll
        for (int it = 0; it < ENC_IPB; it++)
            acc[it] = fmaf(ebuf[it*DIM + k], wv, acc[it]);
    }
    __syncthreads();
#pragma unroll
    for (int it = 0; it < ENC_IPB; it++) hbuf[it*DIM + t] = fmaxf(acc[it], 0.f);
    for (int i = 4*t; i < DIM*DIM; i += 512)
        *(float4*)&ws[i] = *(const float4*)&w2[i];
    __syncthreads();

#pragma unroll
    for (int it = 0; it < ENC_IPB; it++) acc[it] = b2[t];
    for (int k = 0; k < DIM; k++){
        float wv = ws[k*DIM + t];
#pragma unroll
        for (int it = 0; it < ENC_IPB; it++)
            acc[it] = fmaf(hbuf[it*DIM + k], wv, acc[it]);
    }
#pragma unroll
    for (int it = 0; it < ENC_IPB; it++){
        int l = l0 + it;
        g_enc[(b*LQ + l)*DIM + t] = acc[it];
        out[(size_t)b*OW + 2 + LQ*DIM + l*DIM + t] = acc[it];
    }
}

// ---------------- kernel 1bc: fused M=W1z*W3 (blocks 0..63) + JSD (blocks 64..) ----------------
__global__ void pre_k(const float* __restrict__ vw1, const float* __restrict__ vw3,
                      const int* __restrict__ hl)
{
    __shared__ float w3r[8*128];
    int t = threadIdx.x;
    int bx = blockIdx.x;

    if (bx < 64){
        int j0 = bx * 8;
        for (int i = t; i < 8*128; i += 128) w3r[i] = vw3[j0*128 + i];
        __syncthreads();
        float acc[8][4];
#pragma unroll
        for (int jj = 0; jj < 8; jj++)
#pragma unroll
            for (int q = 0; q < 4; q++) acc[jj][q] = 0.f;
        for (int k = 0; k < 128; k++){
            float w1v[4];
#pragma unroll
            for (int q = 0; q < 4; q++) w1v[q] = vw1[k*HID + t + q*128];
#pragma unroll
            for (int jj = 0; jj < 8; jj++){
                float w3v = w3r[jj*128 + k];
#pragma unroll
                for (int q = 0; q < 4; q++) acc[jj][q] = fmaf(w3v, w1v[q], acc[jj][q]);
            }
        }
        for (int jj = 0; jj < 8; jj++)
#pragma unroll
            for (int q = 0; q < 4; q++)
                g_M[(size_t)(j0 + jj)*HID + t + q*128] = acc[jj][q];
        return;
    }

    int idx = bx - 64;
    int b = idx >> 5;
    int w = t >> 5, l = t & 31;
    int j = (idx & 31)*4 + w;
    int n = hl[b]; if (n > LQ) n = LQ;
    if (n < 2*WWIN || j > n - 2*WWIN) return;

    const float4* base = (const float4*)&g_enc[(b*LQ + j)*DIM];
    float4 sL = make_float4(0.f,0.f,0.f,0.f), sR = sL;
#pragma unroll
    for (int r = 0; r < WWIN; r++){
        float4 vL = base[r*32 + l];
        float4 vR = base[(WWIN + r)*32 + l];
        sL.x += vL.x; sL.y += vL.y; sL.z += vL.z; sL.w += vL.w;
        sR.x += vR.x; sR.y += vR.y; sR.z += vR.z; sR.w += vR.w;
    }
    const float inv = 1.f/(float)WWIN;
    sL.x *= inv; sL.y *= inv; sL.z *= inv; sL.w *= inv;
    sR.x *= inv; sR.y *= inv; sR.z *= inv; sR.w *= inv;

    float mL = fmaxf(fmaxf(sL.x, sL.y), fmaxf(sL.z, sL.w));
    float mR = fmaxf(fmaxf(sR.x, sR.y), fmaxf(sR.z, sR.w));
#pragma unroll
    for (int o = 16; o > 0; o >>= 1){
        mL = fmaxf(mL, __shfl_xor_sync(0xffffffffu, mL, o));
        mR = fmaxf(mR, __shfl_xor_sync(0xffffffffu, mR, o));
    }
    float eL0 = expf(sL.x - mL), eL1 = expf(sL.y - mL), eL2 = expf(sL.z - mL), eL3 = expf(sL.w - mL);
    float eR0 = expf(sR.x - mR), eR1 = expf(sR.y - mR), eR2 = expf(sR.z - mR), eR3 = expf(sR.w - mR);
    float suL = (eL0 + eL1) + (eL2 + eL3);
    float suR = (eR0 + eR1) + (eR2 + eR3);
#pragma unroll
    for (int o = 16; o > 0; o >>= 1){
        suL += __shfl_xor_sync(0xffffffffu, suL, o);
        suR += __shfl_xor_sync(0xffffffffu, suR, o);
    }
    float p0 = eL0/suL + 1e-8f, p1 = eL1/suL + 1e-8f, p2 = eL2/suL + 1e-8f, p3 = eL3/suL + 1e-8f;
    float q0 = eR0/suR + 1e-8f, q1 = eR1/suR + 1e-8f, q2 = eR2/suR + 1e-8f, q3 = eR3/suR + 1e-8f;
    float ps = (p0 + p1) + (p2 + p3);
    float qs = (q0 + q1) + (q2 + q3);
#pragma unroll
    for (int o = 16; o > 0; o >>= 1){
        ps += __shfl_xor_sync(0xffffffffu, ps, o);
        qs += __shfl_xor_sync(0xffffffffu, qs, o);
    }
    p0 /= ps; p1 /= ps; p2 /= ps; p3 /= ps;
    q0 /= qs; q1 /= qs; q2 /= qs; q3 /= qs;
    float c = 0.f;
    {
        float m0 = 0.5f*(p0+q0); c += 0.5f*p0*logf(p0/m0) + 0.5f*q0*logf(q0/m0);
        float m1 = 0.5f*(p1+q1); c += 0.5f*p1*logf(p1/m1) + 0.5f*q1*logf(q1/m1);
        float m2 = 0.5f*(p2+q2); c += 0.5f*p2*logf(p2/m2) + 0.5f*q2*logf(q2/m2);
        float m3 = 0.5f*(p3+q3); c += 0.5f*p3*logf(p3/m3) + 0.5f*q3*logf(q3/m3);
    }
#pragma unroll
    for (int o = 16; o > 0; o >>= 1) c += __shfl_xor_sync(0xffffffffu, c, o);
    if (l == 0) g_jsd[b*LQ + j] = c;
}

// ---------------- kernel 2: ballot replay + closed-form parallel grid build ----------------
__global__ void plan_k(const float* __restrict__ ht, const int* __restrict__ hl,
                       const void* __restrict__ p16, const void* __restrict__ p17,
                       const void* __restrict__ p18)
{
    int b = blockIdx.x, t = threadIdx.x;
    const float* pt;
    if (is_index_arr(p16)) pt = (const float*)p18;   // order: pos,neg,pt
    else                   pt = (const float*)p16;   // order: pt,pos,neg

    __shared__ double times[LQ];
    __shared__ unsigned trig[4];
    __shared__ double bounds[MAXSEG + 2];
    __shared__ int starts[MAXSEG + 1];
    __shared__ int mArr[MAXSEG + 1];
    __shared__ int cumArr[MAXSEG + 1];
    __shared__ int segBase[MAXSEG + 1];
    __shared__ int snb, sns, dupF, gapF, sE;
    __shared__ double ev[LQ + 2*MAXSEG + 4];

    int n = hl[b]; if (n > LQ) n = LQ;
    int lim = n - 2*WWIN;
    if (t < n) times[t] = (double)ht[b*LQ + t];
    if (t == 0){ snb = 1; sns = 1; bounds[0] = (double)ht[b*LQ]; starts[0] = 0; dupF = 0; gapF = 0; }
    {
        float jv = (t < LQ) ? g_jsd[b*LQ + t] : 0.f;
        unsigned bal = __ballot_sync(0xffffffffu, (t <= lim) && (jv > 0.5f));
        if ((t & 31) == 0) trig[t >> 5] = bal;
    }
    __syncthreads();
    {
        bool d = (t > 0 && t < n) && (times[t] == times[t-1]);
        if (__ballot_sync(0xffffffffu, d)) dupF = 1;
    }

    if (t == 0 && n >= 2*WWIN){
        int j = 0;
        for (;;){
            if (j > lim) break;
            int wi = j >> 5, sh = j & 31;
            unsigned m = trig[wi];
            if (sh) m &= (0xffffffffu << sh);
            while (!m && wi < 3){ wi++; m = trig[wi]; }
            if (!m) break;
            int f = (wi << 5) + __ffs(m) - 1;
            if (f > lim) break;
            bounds[snb] = 0.5*(times[f + WWIN - 1] + times[f + WWIN]);
            snb++;
            starts[sns] = f + WWIN; sns++;
            j = f + WWIN;
        }
    }
    __syncthreads();
    if (t == 0){
        if (times[n-1] > bounds[snb-1]) { bounds[snb] = times[n-1]; snb++; }
    }
    __syncthreads();

    int nseg = sns, nb2 = snb;

    if (!dupF){
        if (t < nseg){
            int si = t;
            int s = starts[si];
            int e = (si + 1 < nseg) ? starts[si+1] - 1 : n - 1;
            g_segS[b*MAXSEG + si] = s; g_segE[b*MAXSEG + si] = e;
            int d0 = (si == 0) ? 1 : 0;
            int d1 = (si == nseg - 1) ? 1 : 0;
            mArr[si] = (e - s + 1) + 2 - d0 - d1;
        }
        __syncthreads();
        if (t == 0){
            int sb = 0, cum = 0;
            for (int si = 0; si < nseg; si++){
                segBase[si] = sb; cumArr[si] = cum;
                sb += mArr[si]; cum += mArr[si] - 1;
            }
            sE = sb;
            double lb = bounds[nb2-1];
            double ptb = (double)pt[b];
            if (ptb > lb + 1e-6){
                double t1 = ptb;
                if (t1 - lb < 1e-6) t1 = lb + 1e-6;
                g_dt[b*MAXINT + cum] = (float)(t1 - lb);
                g_envSeg[b*MAXINT + cum] = nseg - 1;
                cum++;
            }
            g_nInt[b] = cum;
        }
        __syncthreads();
        int E = sE;
        for (int g = t; g < E; g += 128){
            int si = 0;
            while (si + 1 < nseg && segBase[si+1] <= g) si++;
            int k = g - segBase[si];
            int s = starts[si], d0 = (si == 0) ? 1 : 0;
            double v;
            if (k == 0) v = bounds[si];
            else if (si < nseg - 1 && k == mArr[si] - 1) v = bounds[si+1];
            else v = times[s + d0 + k - 1];
            ev[g] = v;
        }
        __syncthreads();
        {
            bool bad = false;
            for (int g = t; g < E; g += 128){
                int si = 0;
                while (si + 1 < nseg && segBase[si+1] <= g) si++;
                if (g > segBase[si] && ev[g] - ev[g-1] < 1e-6) bad = true;
            }
            if (__ballot_sync(0xffffffffu, bad)) gapF = 1;
        }
        __syncthreads();
        if (gapF && t < nseg){
            int base = segBase[t], m = mArr[t];
            for (int k = 1; k < m; k++)
                if (ev[base + k] - ev[base + k - 1] < 1e-6) ev[base + k] = ev[base + k - 1] + 1e-6;
        }
        if (gapF) __syncthreads();
        for (int g = t; g < E; g += 128){
            int si = 0;
            while (si + 1 < nseg && segBase[si+1] <= g) si++;
            int k = g - segBase[si];
            if (k < mArr[si] - 1){
                g_dt[b*MAXINT + cumArr[si] + k] = (float)(ev[g+1] - ev[g]);
                g_envSeg[b*MAXINT + cumArr[si] + k] = si;
            }
        }
        if (t < n){
            int si = 0;
            while (si + 1 < nseg && starts[si+1] <= t) si++;
            int base = segBase[si], m = mArr[si];
            double ti = times[t];
            int best = 0; double bd = fabs(ev[base] - ti);
            for (int k = 1; k < m; k++){
                double dd = fabs(ev[base + k] - ti);
                if (dd < bd){ bd = dd; best = k; }
            }
            g_gsel[b*LQ + t] = cumArr[si] + best;
        }
    } else {
        if (t < nseg){
            int si = t;
            int s = starts[si];
            int e = (si + 1 < nseg) ? starts[si+1] - 1 : n - 1;
            g_segS[b*MAXSEG + si] = s; g_segE[b*MAXSEG + si] = e;
            double t0 = bounds[si];
            double t1 = (si + 1 < nb2) ? bounds[si+1] : bounds[nb2-1];
            int base = s + 2*si;
            int m = 0; ev[base + m++] = t0;
            for (int i = s; i <= e; i++){
                double d = times[i];
                if (d >= t0 && d <= t1 && d != ev[base + m - 1]) ev[base + m++] = d;
            }
            if (t1 != ev[base + m - 1]) ev[base + m++] = t1;
            for (int k = 1; k < m; k++)
                if (ev[base + k] - ev[base + k - 1] < 1e-6) ev[base + k] = ev[base + k - 1] + 1e-6;
            mArr[si] = m;
        }
        __syncthreads();
        if (t == 0){
            int cum = 0;
            for (int si = 0; si < nseg; si++){ cumArr[si] = cum; cum += mArr[si] - 1; }
            double lb = bounds[nb2-1];
            double ptb = (double)pt[b];
            if (ptb > lb + 1e-6){
                double t1 = ptb;
                if (t1 - lb < 1e-6) t1 = lb + 1e-6;
                g_dt[b*MAXINT + cum] = (float)(t1 - lb);
                g_envSeg[b*MAXINT + cum] = nseg - 1;
                cum++;
            }
            g_nInt[b] = cum;
        }
        __syncthreads();
        if (t < nseg){
            int si = t, base = starts[si] + 2*si;
            int m = mArr[si], cum = cumArr[si];
            for (int k = 0; k < m - 1; k++){
                g_dt[b*MAXINT + cum + k] = (float)(ev[base + k + 1] - ev[base + k]);
                g_envSeg[b*MAXINT + cum + k] = si;
            }
        }
        if (t < n){
            int si = 0;
            while (si + 1 < nseg && starts[si+1] <= t) si++;
            int base = starts[si] + 2*si;
            int m = mArr[si], cum = cumArr[si];
            double ti = times[t];
            int best = 0; double bd = fabs(ev[base] - ti);
            for (int k = 1; k < m; k++){
                double dd = fabs(ev[base + k] - ti);
                if (dd < bd){ bd = dd; best = k; }
            }
            g_gsel[b*LQ + t] = cum + best;
        }
    }
}

// ---------------- kernel 3: clustered Euler ODE (R14 reduces, warp0-burst sends) ----------------
struct __align__(16) OdeSmem {
    unsigned long long mb[4];   // 0: h1, 1: h2, 2: score, 3: pad
    float mt[32*MTP];           // M slice transposed [o][j] (66KB); staging at init
    float w3s[8*MTP];           // W3 slice [i][j]
    float cenvAll[MAXSEG*32];
    float env[DIM];             // z0 staging
    float h1[HID];              // receive buffer (chunk c written by CTA c)
    float h2[HID];              // receive buffer
    float partA[16*32];         // L2 partials [q][o] (conflict-free)
    float partB[16*32];         // M partials [q][o]
    float p2[16*8];             // W3 partials
    float sc[32];               // fused-score partials (rank0 only receives)
    float zs[8];
    float b2s[32];
    float c3s[32];
    float b3s[8];
    float aval[32];
    float dtv[MAXINT];
    int   eseg[MAXINT];
    int   segS[MAXSEG];
    int   segE[MAXSEG];
    int   gsel[LQ];
};

extern __shared__ __align__(16) char ode_raw[];

#define XCHG_TX (2048u)   // 16 CTAs x 32 floats x 4B per phase

__global__ void __launch_bounds__(TPB2, 1) __cluster_dims__(CL, 1, 1)
ode_cl_k(const float* __restrict__ usert, const int* __restrict__ u,
         const float* __restrict__ vw1, const float* __restrict__ vb1,
         const float* __restrict__ vw2, const float* __restrict__ vb2,
         const float* __restrict__ vw3, const float* __restrict__ vb3,
         const int* __restrict__ hl, const float* __restrict__ emb,
         const void* __restrict__ p16, const void* __restrict__ p17,
         const void* __restrict__ p18,
         float* __restrict__ out)
{
    OdeSmem* S = (OdeSmem*)ode_raw;
    int t = threadIdx.x;
    uint32_t cr; asm("mov.u32 %0, %%cluster_ctarank;" : "=r"(cr));
    int b = blockIdx.x / CL;

    const int o32 = t & 31, p16g = t >> 5;   // 32 outs x 16 k-parts
    const int o8w = t & 7,  i64  = t >> 3;   // traj-write mapping

    const int *pos, *neg;
    if (is_index_arr(p16)) { pos = (const int*)p16; neg = (const int*)p17; }
    else                   { pos = (const int*)p17; neg = (const int*)p18; }

    // ---- layer-2 weight slice into registers (32 floats = 16 f32x2) ----
    ull w2p[16];
    {
        const float* base = &vw2[(size_t)(p16g*32)*HID + cr*32 + o32];
#pragma unroll
        for (int m = 0; m < 16; m++)
            w2p[m] = pack2(base[(size_t)(2*m)*HID], base[(size_t)(2*m+1)*HID]);
    }

    // ---- stage W1 z-half & env-half slices in mt space (freed before mt load) ----
    float* wz   = S->mt;              // [128][32]
    float* wenv = S->mt + 4096;       // [128][32]
    for (int idx = t; idx < 4096; idx += TPB2){
        int k = idx >> 5, o = idx & 31;
        wz[k*32 + o]   = vw1[(size_t)k*HID + cr*32 + o];
        wenv[k*32 + o] = vw1[(size_t)(DIM + k)*HID + cr*32 + o];
    }
    if (t < DIM) S->env[t] = usert[(size_t)u[b]*DIM + t];   // z0
    for (int i = t; i < MAXINT; i += TPB2){
        S->dtv[i]  = g_dt[b*MAXINT + i];
        S->eseg[i] = g_envSeg[b*MAXINT + i];
    }
    for (int i = t; i < MAXSEG; i += TPB2){
        S->segS[i] = g_segS[b*MAXSEG + i];
        S->segE[i] = g_segE[b*MAXSEG + i];
    }
    for (int i = t; i < LQ; i += TPB2) S->gsel[i] = g_gsel[b*LQ + i];
    if (t < 32) S->b2s[t] = vb2[cr*32 + t];
    if (t < 8)  S->b3s[t] = vb3[cr*8 + t];
    __syncthreads();

    // ---- a0 = W1z·z0 and c3 = W1z·b3 (16 k-parts of 8) ----
    {
        float az = 0.f, ac = 0.f;
        const float* wp = &wz[(p16g*8)*32 + o32];
        const float* zp = &S->env[p16g*8];
#pragma unroll
        for (int kk = 0; kk < 8; kk++){
            float wv = wp[kk*32];
            az = fmaf(zp[kk], wv, az);
            ac = fmaf(vb3[p16g*8 + kk], wv, ac);
        }
        S->partA[p16g*32 + o32] = az;
        S->partB[p16g*32 + o32] = ac;
    }
    __syncthreads();
    if (t < 32){
        float sa = 0.f, sc = 0.f;
#pragma unroll
        for (int q = 0; q < 16; q++){ sa += S->partA[q*32 + t]; sc += S->partB[q*32 + t]; }
        S->aval[t] = sa; S->c3s[t] = sc;
    }
    __syncthreads();

    int nInt = g_nInt[b];
    int nseg = S->eseg[nInt - 1] + 1;
    int n = hl[b]; if (n > LQ) n = LQ;

    // ---- per-segment cenv = vb1 + Wenv·mean(enc[s..e]) ----
    for (int si = 0; si < nseg; si++){
        int s = S->segS[si], e = S->segE[si];
        if (t < DIM){
            float a = 0.f;
            for (int r2 = s; r2 <= e; r2++) a += g_enc[(b*LQ + r2)*DIM + t];
            S->h1[t] = a / (float)(e - s + 1);
        }
        __syncthreads();
        {
            float a = 0.f;
            const float* wp = &wenv[(p16g*8)*32 + o32];
            const float* ep = &S->h1[p16g*8];
#pragma unroll
            for (int kk = 0; kk < 8; kk++) a = fmaf(ep[kk], wp[kk*32], a);
            S->partA[p16g*32 + o32] = a;
        }
        __syncthreads();
        if (t < 32){
            float sa = 0.f;
#pragma unroll
            for (int q = 0; q < 16; q++) sa += S->partA[q*32 + t];
            S->cenvAll[si*32 + t] = vb1[cr*32 + t] + sa;
        }
        __syncthreads();
    }

    // ---- load M slice (overwrites staging) + W3 slice + z slice ----
    for (int idx = t; idx < 32*HID; idx += TPB2){
        int jj = idx >> 5, o = idx & 31;
        S->mt[o*MTP + jj] = g_M[(size_t)jj*HID + cr*32 + o];
    }
    for (int idx = t; idx < 8*HID; idx += TPB2){
        int jj = idx >> 3, o = idx & 7;
        S->w3s[o*MTP + jj] = vw3[jj*DIM + cr*8 + o];
    }
    if (t < 8) S->zs[t] = S->env[cr*8 + t];

    uint32_t mb_h1 = smem_u32(&S->mb[0]);
    uint32_t mb_h2 = smem_u32(&S->mb[1]);
    uint32_t mb_sc = smem_u32(&S->mb[2]);
    if (t == 0){ mbar_init(mb_h1, 1); mbar_init(mb_h2, 1); mbar_init(mb_sc, 1); }
    __syncthreads();
    if (t == 0){
        mbar_expect(mb_h1, XCHG_TX);
        mbar_expect(mb_h2, XCHG_TX);
        if (cr == 0) mbar_expect(mb_sc, 32*4);
    }
    __syncthreads();
    CLUSTER_SYNC_();

    // t<32 recurrent state registers
    float avreg = 0.f, c3reg = 0.f, b2reg = 0.f;
    if (t < 32){ avreg = S->aval[t]; c3reg = S->c3s[t]; b2reg = S->b2s[t]; }

    uint32_t la_h1 = smem_u32(&S->h1[cr*32 + o32]);   // slot for value o32 (t<32: o32==t)
    uint32_t la_h2 = smem_u32(&S->h2[cr*32 + o32]);

    // grid-0 state writes (z0 slice)
    {
#pragma unroll
        for (int pass = 0; pass < 2; pass++){
            int i = pass*64 + i64;
            if (i < n && S->gsel[i] == 0)
                out[(size_t)b*OW + 2 + (size_t)i*DIM + cr*8 + o8w] = S->zs[o8w];
        }
    }

    int totalSS = 2*nInt;
    // prologue: warp0 computes h1 for substep 0 and bursts to all 16 ranks
    if (t < 32){
        float hv = softplusf(S->cenvAll[S->eseg[0]*32 + t] + avreg);
#pragma unroll
        for (int d = 0; d < CL; d++)
            st_async_f(mapa_u32(la_h1, d), mapa_u32(mb_h1, d), hv);
    }

    for (int ss = 0; ss < totalSS; ss++){
        int j = ss >> 1;
        float dtsub = 0.5f * S->dtv[j];
        uint32_t par = (uint32_t)(ss & 1);

        mbar_wait(mb_h1, par);
        if (t == 0) mbar_expect(mb_h1, XCHG_TX);
        // ---- layer 2: 32 out x 512 k, f32x2 packed, weights in registers ----
        {
            const ulonglong2* hr = (const ulonglong2*)&S->h1[p16g*32];
            ull acc0 = 0ull, acc1 = 0ull;
#pragma unroll
            for (int m = 0; m < 8; m++){
                ulonglong2 h = hr[m];
                acc0 = ffma2(w2p[2*m],   h.x, acc0);
                acc1 = ffma2(w2p[2*m+1], h.y, acc1);
            }
            S->partA[p16g*32 + o32] = unpack_sum(acc0) + unpack_sum(acc1);
        }
        __syncthreads();   // S1: L2 partials complete
        if (t < 32){
            float sa = 0.f;
#pragma unroll
            for (int q = 0; q < 16; q++) sa += S->partA[q*32 + t];
            float hv = softplusf(b2reg + sa);
#pragma unroll
            for (int d = 0; d < CL; d++)
                st_async_f(mapa_u32(la_h2, d), mapa_u32(mb_h2, d), hv);
        }
        mbar_wait(mb_h2, par);
        if (t == 0) mbar_expect(mb_h2, XCHG_TX);
        // ---- M·h2 partials (all threads) + W3·h2 partials (t<128) ----
        {
            const ulonglong2* wr = (const ulonglong2*)&S->mt[o32*MTP + p16g*32];
            const ulonglong2* hr = (const ulonglong2*)&S->h2[p16g*32];
            ull acc0 = 0ull, acc1 = 0ull;
#pragma unroll
            for (int m = 0; m < 8; m++){
                ulonglong2 w = wr[m];
                ulonglong2 h = hr[m];
                acc0 = ffma2(w.x, h.x, acc0);
                acc1 = ffma2(w.y, h.y, acc1);
            }
            S->partB[p16g*32 + o32] = unpack_sum(acc0) + unpack_sum(acc1);
        }
        if (t < 128){
            int o8d = t & 7, pp = t >> 3;
            const ulonglong2* wr = (const ulonglong2*)&S->w3s[o8d*MTP + pp*32];
            const ulonglong2* hr = (const ulonglong2*)&S->h2[pp*32];
            ull acc0 = 0ull;
#pragma unroll
            for (int m = 0; m < 8; m++){
                ulonglong2 w = wr[m];
                ulonglong2 h = hr[m];
                acc0 = ffma2(w.x, h.x, acc0);
                acc0 = ffma2(w.y, h.y, acc0);
            }
            S->p2[pp*8 + o8d] = unpack_sum(acc0);
        }
        __syncthreads();   // S2: M + W3 partials complete
        if (t < 32){
            float tot = 0.f;
#pragma unroll
            for (int q = 0; q < 16; q++) tot += S->partB[q*32 + t];
            avreg += dtsub * (c3reg + tot);
            if (ss + 1 < totalSS){
                int jn = (ss + 1) >> 1;
                float hv = softplusf(S->cenvAll[S->eseg[jn]*32 + t] + avreg);
#pragma unroll
                for (int d = 0; d < CL; d++)
                    st_async_f(mapa_u32(la_h1, d), mapa_u32(mb_h1, d), hv);
            }
        } else if (t < 40){
            int i = t - 32;
            float dv = S->b3s[i];
#pragma unroll
            for (int q = 0; q < 16; q++) dv += S->p2[q*8 + i];
            S->zs[i] += dtsub * dv;
        }
        if (ss & 1){   // end of interval j: write matched interaction states
            __syncthreads();   // zs visible to all traj writers
            int g = j + 1;
#pragma unroll
            for (int pass = 0; pass < 2; pass++){
                int i = pass*64 + i64;
                if (i < n && S->gsel[i] == g)
                    out[(size_t)b*OW + 2 + (size_t)i*DIM + cr*8 + o8w] = S->zs[o8w];
            }
        }
    }

    __syncthreads();
    // ---- fused scores: each CTA sends 2 partial dots to rank 0 ----
    if (t == 0){
        float sp = 0.f, sn = 0.f;
        const float* ep = &emb[(size_t)pos[b]*DIM + cr*8];
        const float* en = &emb[(size_t)neg[b]*DIM + cr*8];
#pragma unroll
        for (int i = 0; i < 8; i++){
            sp = fmaf(S->zs[i], ep[i], sp);
            sn = fmaf(S->zs[i], en[i], sn);
        }
        st_async_f(mapa_u32(smem_u32(&S->sc[cr]), 0),      mapa_u32(mb_sc, 0), sp);
        st_async_f(mapa_u32(smem_u32(&S->sc[16 + cr]), 0), mapa_u32(mb_sc, 0), sn);
    }
    if (cr == 0 && t == 0){
        mbar_wait(mb_sc, 0);
        float sp = 0.f, sn = 0.f;
        for (int r = 0; r < CL; r++){ sp += S->sc[r]; sn += S->sc[16 + r]; }
        out[(size_t)b*OW]     = sp;
        out[(size_t)b*OW + 1] = sn;
    }
    CLUSTER_SYNC_();
    if (t == 0){ mbar_inval(mb_h1); mbar_inval(mb_h2); mbar_inval(mb_sc); }
}

// ---------------- launch ----------------
extern "C" void kernel_launch(void* const* d_in, const int* in_sizes, int n_in,
                              void* d_out, int out_size)
{
    const float* emb   = (const float*)d_in[0];
    const float* mw1   = (const float*)d_in[1];
    const float* mb1   = (const float*)d_in[2];
    const float* mw2   = (const float*)d_in[3];
    const float* mb2   = (const float*)d_in[4];
    const float* usert = (const float*)d_in[5];
    const float* vw1   = (const float*)d_in[6];
    const float* vb1   = (const float*)d_in[7];
    const float* vw2   = (const float*)d_in[8];
    const float* vb2   = (const float*)d_in[9];
    const float* vw3   = (const float*)d_in[10];
    const float* vb3   = (const float*)d_in[11];
    const int*   u     = (const int*)d_in[12];
    const int*   hi    = (const int*)d_in[13];
    const float* ht    = (const float*)d_in[14];
    const int*   hl    = (const int*)d_in[15];
    const void*  p16   = d_in[16];
    const void*  p17   = d_in[17];
    const void*  p18   = d_in[18];
    float* out = (float*)d_out;

    static int attrs_set = 0;
    if (!attrs_set){
        cudaFuncSetAttribute(ode_cl_k, cudaFuncAttributeMaxDynamicSharedMemorySize,
                             (int)sizeof(OdeSmem));
        cudaFuncSetAttribute(ode_cl_k, cudaFuncAttributeNonPortableClusterSizeAllowed, 1);
        cudaFuncSetAttribute(enc_k, cudaFuncAttributeMaxDynamicSharedMemorySize, ENC_SMEM);
        attrs_set = 1;
    }

    dim3 ge(LQ/ENC_IPB, NB);
    enc_k<<<ge, DIM, ENC_SMEM>>>(hi, emb, mw1, mb1, mw2, mb2, out);
    pre_k<<<64 + NB*32, 128>>>(vw1, vw3, hl);
    plan_k<<<NB, 128>>>(ht, hl, p16, p17, p18);
    ode_cl_k<<<NB*CL, TPB2, sizeof(OdeSmem)>>>(usert, u, vw1, vb1, vw2, vb2, vw3, vb3,
                                               hl, emb, p16, p17, p18, out);
}